// round 1
// baseline (speedup 1.0000x reference)
#include <cuda_runtime.h>

// Problem constants
#define NB    2
#define NTOK  2048
#define DIMM  512
#define NH    8
#define DHD   64
#define MTOK  3
#define SQRT_DH 8.0f
#define SQRT_M  1.7320508075688772f
#define SCALE   0.125f

// Scratch (no cudaMalloc allowed)
__device__ float g_q[NB * NTOK * DIMM];          // 8 MB  (b*n, h*d)
__device__ float g_kv[NB * NTOK * 2 * DIMM];     // 16 MB (b*n, [k|v])
__device__ float g_attn[NB * NTOK * DIMM];       // 8 MB  (b*n, h*d)

// ---------------------------------------------------------------------------
// Tiled SGEMM: C[M,N] = A[M,512] @ B[512,N] (+ bias). BM=BN=64, BK=16,
// 256 threads, 4x4 register tile per thread. M,N multiples of 64.
// ---------------------------------------------------------------------------
__global__ void __launch_bounds__(256) sgemm_kernel(
    const float* __restrict__ A, const float* __restrict__ Bm,
    float* __restrict__ C, const float* __restrict__ bias, int Ncols)
{
    __shared__ float As[16][65];   // [kk][row], padded
    __shared__ float Bs[16][64];   // [kk][col]
    const int K = 512;
    const int tid  = threadIdx.x;
    const int row0 = blockIdx.y * 64;
    const int col0 = blockIdx.x * 64;
    const int tr = tid >> 4;       // 0..15 -> 4 rows each
    const int tc = tid & 15;       // 0..15 -> 4 cols each

    float acc[4][4];
#pragma unroll
    for (int i = 0; i < 4; i++)
#pragma unroll
        for (int j = 0; j < 4; j++) acc[i][j] = 0.0f;

    for (int k0 = 0; k0 < K; k0 += 16) {
        // Load A tile 64x16 (float4 per thread)
        {
            int r  = tid >> 2;
            int c4 = (tid & 3) * 4;
            float4 v = *reinterpret_cast<const float4*>(A + (row0 + r) * K + k0 + c4);
            As[c4 + 0][r] = v.x; As[c4 + 1][r] = v.y;
            As[c4 + 2][r] = v.z; As[c4 + 3][r] = v.w;
        }
        // Load B tile 16x64 (float4 per thread)
        {
            int r  = tid >> 4;
            int c4 = (tid & 15) * 4;
            *reinterpret_cast<float4*>(&Bs[r][c4]) =
                *reinterpret_cast<const float4*>(Bm + (k0 + r) * Ncols + col0 + c4);
        }
        __syncthreads();
#pragma unroll
        for (int kk = 0; kk < 16; kk++) {
            float a[4], b[4];
#pragma unroll
            for (int i = 0; i < 4; i++) a[i] = As[kk][tr * 4 + i];
#pragma unroll
            for (int j = 0; j < 4; j++) b[j] = Bs[kk][tc * 4 + j];
#pragma unroll
            for (int i = 0; i < 4; i++)
#pragma unroll
                for (int j = 0; j < 4; j++) acc[i][j] += a[i] * b[j];
        }
        __syncthreads();
    }

#pragma unroll
    for (int i = 0; i < 4; i++) {
        int r = row0 + tr * 4 + i;
#pragma unroll
        for (int j = 0; j < 4; j++) {
            int c = col0 + tc * 4 + j;
            float v = acc[i][j];
            if (bias) v += bias[c];
            C[r * Ncols + c] = v;
        }
    }
}

// ---------------------------------------------------------------------------
// Flash attention: per (b,h) pair, 64-query tiles, 64-key tiles + a final
// 3-key memory-token tile. 256 threads; thread grid 16x16; 4x4 register
// tiles for both S = Q K^T and O += P V. Online softmax, row stats shared
// across 16-lane groups via shfl.
// ---------------------------------------------------------------------------
#define LD 65

__global__ void __launch_bounds__(256) attn_kernel(
    const float* __restrict__ q, const float* __restrict__ kv,
    const float* __restrict__ mk, const float* __restrict__ mv,
    float* __restrict__ out)
{
    extern __shared__ float sm[];
    float* Qs = sm;                  // 64 x LD
    float* Ks = Qs + 64 * LD;
    float* Vs = Ks + 64 * LD;
    float* Ps = Vs + 64 * LD;

    const int tid = threadIdx.x;
    const int bh  = blockIdx.y;
    const int b   = bh >> 3;
    const int h   = bh & 7;
    const int q0  = blockIdx.x * 64;

    const int tq = tid >> 4;   // 0..15 : query group (4 rows)
    const int tx = tid & 15;   // 0..15 : key group / dim group (4 cols)

    // Load Q tile, pre-scaled by SCALE
    for (int i = tid; i < 64 * 64; i += 256) {
        int rr = i >> 6, dd = i & 63;
        Qs[rr * LD + dd] = q[(b * NTOK + q0 + rr) * DIMM + h * DHD + dd] * SCALE;
    }

    float acc[4][4];
#pragma unroll
    for (int i = 0; i < 4; i++)
#pragma unroll
        for (int j = 0; j < 4; j++) acc[i][j] = 0.0f;
    float mi[4], li[4];
#pragma unroll
    for (int i = 0; i < 4; i++) { mi[i] = -1e30f; li[i] = 0.0f; }

    __syncthreads();

    for (int t = 0; t < 33; t++) {
        // Load K,V tile (tile 32 = the 3 memory tokens)
        for (int i = tid; i < 64 * 64; i += 256) {
            int kk = i >> 6, dd = i & 63;
            float kval, vval;
            if (t < 32) {
                int base = (b * NTOK + t * 64 + kk) * (2 * DIMM);
                kval = kv[base + h * DHD + dd];
                vval = kv[base + DIMM + h * DHD + dd];
            } else if (kk < MTOK) {
                int idx = h * (MTOK * DHD) + kk * DHD + dd;  // flat-reshape indexing
                kval = SQRT_DH * mk[idx];
                vval = SQRT_M  * mv[idx];
            } else {
                kval = 0.0f; vval = 0.0f;
            }
            Ks[kk * LD + dd] = kval;
            Vs[kk * LD + dd] = vval;
        }
        __syncthreads();

        // S = Q K^T for this thread's 4x4 block
        float s[4][4];
#pragma unroll
        for (int i = 0; i < 4; i++)
#pragma unroll
            for (int j = 0; j < 4; j++) s[i][j] = 0.0f;

#pragma unroll 16
        for (int d = 0; d < 64; d++) {
            float a[4], bb[4];
#pragma unroll
            for (int i = 0; i < 4; i++) a[i]  = Qs[(tq * 4 + i) * LD + d];
#pragma unroll
            for (int j = 0; j < 4; j++) bb[j] = Ks[(tx * 4 + j) * LD + d];
#pragma unroll
            for (int i = 0; i < 4; i++)
#pragma unroll
                for (int j = 0; j < 4; j++) s[i][j] += a[i] * bb[j];
        }

        // Mask invalid keys in the memory-token tile
        if (t == 32) {
#pragma unroll
            for (int j = 0; j < 4; j++) {
                if (tx * 4 + j >= MTOK) {
#pragma unroll
                    for (int i = 0; i < 4; i++) s[i][j] = -1e30f;
                }
            }
        }

        // Online softmax per query row (reduce over 16 lanes of the tq group)
#pragma unroll
        for (int i = 0; i < 4; i++) {
            float tm = s[i][0];
#pragma unroll
            for (int j = 1; j < 4; j++) tm = fmaxf(tm, s[i][j]);
            tm = fmaxf(tm, __shfl_xor_sync(0xffffffffu, tm, 1));
            tm = fmaxf(tm, __shfl_xor_sync(0xffffffffu, tm, 2));
            tm = fmaxf(tm, __shfl_xor_sync(0xffffffffu, tm, 4));
            tm = fmaxf(tm, __shfl_xor_sync(0xffffffffu, tm, 8));
            float mnew = fmaxf(mi[i], tm);
            float ps = 0.0f;
#pragma unroll
            for (int j = 0; j < 4; j++) {
                float p = __expf(s[i][j] - mnew);
                s[i][j] = p;
                ps += p;
            }
            ps += __shfl_xor_sync(0xffffffffu, ps, 1);
            ps += __shfl_xor_sync(0xffffffffu, ps, 2);
            ps += __shfl_xor_sync(0xffffffffu, ps, 4);
            ps += __shfl_xor_sync(0xffffffffu, ps, 8);
            float alpha = __expf(mi[i] - mnew);
            li[i] = li[i] * alpha + ps;
            mi[i] = mnew;
#pragma unroll
            for (int j = 0; j < 4; j++) acc[i][j] *= alpha;
        }

        // Publish P to smem
#pragma unroll
        for (int i = 0; i < 4; i++)
#pragma unroll
            for (int j = 0; j < 4; j++)
                Ps[(tq * 4 + i) * LD + tx * 4 + j] = s[i][j];
        __syncthreads();

        // O += P V  (dims: tx*4+j)
#pragma unroll 16
        for (int k = 0; k < 64; k++) {
            float p[4], v[4];
#pragma unroll
            for (int i = 0; i < 4; i++) p[i] = Ps[(tq * 4 + i) * LD + k];
#pragma unroll
            for (int j = 0; j < 4; j++) v[j] = Vs[k * LD + tx * 4 + j];
#pragma unroll
            for (int i = 0; i < 4; i++)
#pragma unroll
                for (int j = 0; j < 4; j++) acc[i][j] += p[i] * v[j];
        }
        __syncthreads();  // before next tile overwrites Ks/Vs/Ps
    }

    // Normalize and write to (b*n, h*d) layout
#pragma unroll
    for (int i = 0; i < 4; i++) {
        float inv = 1.0f / li[i];
        int row = b * NTOK + q0 + tq * 4 + i;
#pragma unroll
        for (int j = 0; j < 4; j++)
            out[row * DIMM + h * DHD + tx * 4 + j] = acc[i][j] * inv;
    }
}

// ---------------------------------------------------------------------------
extern "C" void kernel_launch(void* const* d_in, const int* in_sizes, int n_in,
                              void* d_out, int out_size)
{
    const float* x   = (const float*)d_in[0];
    const float* wq  = (const float*)d_in[1];
    const float* wkv = (const float*)d_in[2];
    const float* wo  = (const float*)d_in[3];
    const float* bo  = (const float*)d_in[4];
    const float* m_k = (const float*)d_in[5];
    const float* m_v = (const float*)d_in[6];
    float* out = (float*)d_out;

    float *pq, *pkv, *pattn;
    cudaGetSymbolAddress((void**)&pq,    g_q);
    cudaGetSymbolAddress((void**)&pkv,   g_kv);
    cudaGetSymbolAddress((void**)&pattn, g_attn);

    const int MROWS = NB * NTOK;  // 4096

    // Projections
    {
        dim3 grid(DIMM / 64, MROWS / 64);
        sgemm_kernel<<<grid, 256>>>(x, wq, pq, nullptr, DIMM);
    }
    {
        dim3 grid((2 * DIMM) / 64, MROWS / 64);
        sgemm_kernel<<<grid, 256>>>(x, wkv, pkv, nullptr, 2 * DIMM);
    }

    // Attention
    {
        size_t smem = 4 * 64 * LD * sizeof(float);  // 66560 B
        cudaFuncSetAttribute(attn_kernel,
                             cudaFuncAttributeMaxDynamicSharedMemorySize,
                             (int)smem);
        dim3 grid(NTOK / 64, NB * NH);
        attn_kernel<<<grid, 256, smem>>>(pq, pkv, m_k, m_v, pattn);
    }

    // Output projection (+bias)
    {
        dim3 grid(DIMM / 64, MROWS / 64);
        sgemm_kernel<<<grid, 256>>>(pattn, wo, out, bo, DIMM);
    }
}

// round 3
// speedup vs baseline: 2.9597x; 2.9597x over previous
#include <cuda_runtime.h>
#include <cuda_bf16.h>
#include <cstdint>

// Problem constants
#define NB    2
#define NTOK  2048
#define DIMM  512
#define NH    8
#define DHD   64
#define MTOK  3
#define SQRT_DH 8.0f
#define SQRT_M  1.7320508075688772f
#define SCALE   0.125f
#define LOG2E   1.4426950408889634f
#define MROWS (NB * NTOK)   // 4096
#define KDIM  512

// ---------------------------------------------------------------------------
// Scratch (__device__ globals; no cudaMalloc allowed). All bf16 hi/lo pairs.
// ---------------------------------------------------------------------------
__device__ __nv_bfloat16 g_xh[MROWS * KDIM],      g_xl[MROWS * KDIM];
__device__ __nv_bfloat16 g_qh[MROWS * DIMM],      g_ql[MROWS * DIMM];
__device__ __nv_bfloat16 g_kvh[MROWS * 2 * DIMM], g_kvl[MROWS * 2 * DIMM];
__device__ __nv_bfloat16 g_oh[MROWS * DIMM],      g_ol[MROWS * DIMM];
__device__ __nv_bfloat16 g_wqh[KDIM * DIMM],      g_wql[KDIM * DIMM];
__device__ __nv_bfloat16 g_wkvh[KDIM * 2 * DIMM], g_wkvl[KDIM * 2 * DIMM];
__device__ __nv_bfloat16 g_woh[KDIM * DIMM],      g_wol[KDIM * DIMM];

// ---------------------------------------------------------------------------
// Warp-MMA primitives (generic sm_80+ PTX: ldmatrix + mma.sync bf16)
// ---------------------------------------------------------------------------
__device__ __forceinline__ uint32_t smem_u32(const void* p) {
    uint32_t a;
    asm("{ .reg .u64 t; cvta.to.shared.u64 t, %1; cvt.u32.u64 %0, t; }" : "=r"(a) : "l"(p));
    return a;
}
__device__ __forceinline__ void ldsm4(uint32_t* r, uint32_t a) {
    asm volatile("ldmatrix.sync.aligned.m8n8.x4.shared.b16 {%0,%1,%2,%3}, [%4];"
                 : "=r"(r[0]), "=r"(r[1]), "=r"(r[2]), "=r"(r[3]) : "r"(a));
}
__device__ __forceinline__ void ldsm4t(uint32_t* r, uint32_t a) {
    asm volatile("ldmatrix.sync.aligned.m8n8.x4.trans.shared.b16 {%0,%1,%2,%3}, [%4];"
                 : "=r"(r[0]), "=r"(r[1]), "=r"(r[2]), "=r"(r[3]) : "r"(a));
}
__device__ __forceinline__ void mma16816(float* c, const uint32_t* a, const uint32_t* b) {
    asm volatile(
        "mma.sync.aligned.m16n8k16.row.col.f32.bf16.bf16.f32 "
        "{%0,%1,%2,%3}, {%4,%5,%6,%7}, {%8,%9}, {%0,%1,%2,%3};"
        : "+f"(c[0]), "+f"(c[1]), "+f"(c[2]), "+f"(c[3])
        : "r"(a[0]), "r"(a[1]), "r"(a[2]), "r"(a[3]), "r"(b[0]), "r"(b[1]));
}
__device__ __forceinline__ float fast_exp2(float x) {
    float r;
    asm("ex2.approx.f32 %0, %1;" : "=f"(r) : "f"(x));
    return r;
}
__device__ __forceinline__ void pack_split(float x, float y, uint32_t& h, uint32_t& l) {
    __nv_bfloat162 hh = __floats2bfloat162_rn(x, y);
    float2 hf = __bfloat1622float2(hh);
    __nv_bfloat162 ll = __floats2bfloat162_rn(x - hf.x, y - hf.y);
    h = reinterpret_cast<uint32_t&>(hh);
    l = reinterpret_cast<uint32_t&>(ll);
}

// ---------------------------------------------------------------------------
// Prep kernels
// ---------------------------------------------------------------------------
__global__ void __launch_bounds__(256) split_scale_kernel(
    const float* __restrict__ in, __nv_bfloat16* __restrict__ hi,
    __nv_bfloat16* __restrict__ lo, int n, float scale)
{
    int i = (blockIdx.x * 256 + threadIdx.x) * 4;
    if (i >= n) return;
    float4 v = *reinterpret_cast<const float4*>(in + i);
    v.x *= scale; v.y *= scale; v.z *= scale; v.w *= scale;
    uint32_t h0, l0, h1, l1;
    pack_split(v.x, v.y, h0, l0);
    pack_split(v.z, v.w, h1, l1);
    *reinterpret_cast<uint32_t*>(hi + i)     = h0;
    *reinterpret_cast<uint32_t*>(hi + i + 2) = h1;
    *reinterpret_cast<uint32_t*>(lo + i)     = l0;
    *reinterpret_cast<uint32_t*>(lo + i + 2) = l1;
}

// W[K][N] -> Th[N][K], Tl[N][K]
__global__ void __launch_bounds__(256) transpose_split_kernel(
    const float* __restrict__ W, __nv_bfloat16* __restrict__ Th,
    __nv_bfloat16* __restrict__ Tl, int K, int N)
{
    int idx = blockIdx.x * 256 + threadIdx.x;
    if (idx >= K * N) return;
    int k = idx / N, n = idx % N;
    float v = W[idx];
    __nv_bfloat16 h = __float2bfloat16(v);
    Th[n * K + k] = h;
    Tl[n * K + k] = __float2bfloat16(v - __bfloat162float(h));
}

// ---------------------------------------------------------------------------
// HMMA GEMM: C[M,N] = A[M,512] @ B[512,N], A/B pre-split bf16, B transposed
// to [N][K]. CTA 128x128, 8 warps (32x64 each), BK=64, padded smem stride 72.
// Output: either fp32 (+bias) or bf16 hi/lo (scaled).
// ---------------------------------------------------------------------------
#define GP 72

__global__ void __launch_bounds__(256) mma_gemm_kernel(
    const __nv_bfloat16* __restrict__ Ah, const __nv_bfloat16* __restrict__ Al,
    const __nv_bfloat16* __restrict__ BTh, const __nv_bfloat16* __restrict__ BTl,
    float* __restrict__ Cf, const float* __restrict__ bias,
    __nv_bfloat16* __restrict__ Ch, __nv_bfloat16* __restrict__ Cl,
    float oscale, int Ncols)
{
    extern __shared__ __nv_bfloat16 sm[];
    // layout: sAh [128*GP] | sAl | sBh | sBl
    const int tid = threadIdx.x, wid = tid >> 5, lane = tid & 31;
    const int row0 = blockIdx.y * 128, col0 = blockIdx.x * 128;
    const int wm = (wid & 3) * 32, wn = (wid >> 2) * 64;
    const uint32_t base = smem_u32(sm);
    const uint32_t offAl = 128 * GP * 2, offBh = 2 * 128 * GP * 2, offBl = 3 * 128 * GP * 2;

    float acc[2][8][4];
#pragma unroll
    for (int mt = 0; mt < 2; mt++)
#pragma unroll
        for (int nt = 0; nt < 8; nt++)
#pragma unroll
            for (int j = 0; j < 4; j++) acc[mt][nt][j] = 0.0f;

    for (int chunk = 0; chunk < 8; chunk++) {
        int k0 = chunk * 64;
        __syncthreads();
#pragma unroll
        for (int it = 0; it < 4; it++) {
            int i = tid + it * 256;         // 0..1023
            int r = i >> 3, u = i & 7;
            size_t ga = (size_t)(row0 + r) * KDIM + k0 + u * 8;
            size_t gb = (size_t)(col0 + r) * KDIM + k0 + u * 8;
            *reinterpret_cast<uint4*>(sm + r * GP + u * 8)                = *reinterpret_cast<const uint4*>(Ah + ga);
            *reinterpret_cast<uint4*>(sm + 128 * GP + r * GP + u * 8)     = *reinterpret_cast<const uint4*>(Al + ga);
            *reinterpret_cast<uint4*>(sm + 2 * 128 * GP + r * GP + u * 8) = *reinterpret_cast<const uint4*>(BTh + gb);
            *reinterpret_cast<uint4*>(sm + 3 * 128 * GP + r * GP + u * 8) = *reinterpret_cast<const uint4*>(BTl + gb);
        }
        __syncthreads();

        const int lr = lane & 15, lc = (lane >> 4) * 8;
#pragma unroll
        for (int kt = 0; kt < 4; kt++) {
            uint32_t ah[2][4], al[2][4];
#pragma unroll
            for (int mt = 0; mt < 2; mt++) {
                uint32_t ad = base + (uint32_t)(((wm + mt * 16 + lr) * GP + kt * 16 + lc) * 2);
                ldsm4(ah[mt], ad);
                ldsm4(al[mt], ad + offAl);
            }
#pragma unroll
            for (int np = 0; np < 4; np++) {
                uint32_t r4[4], l4[4];
                uint32_t bd = base + offBh + (uint32_t)(((wn + np * 16 + lr) * GP + kt * 16 + lc) * 2);
                ldsm4(r4, bd);
                ldsm4(l4, bd + (offBl - offBh));
                uint32_t bh0[2] = {r4[0], r4[2]}, bh1[2] = {r4[1], r4[3]};
                uint32_t bl0[2] = {l4[0], l4[2]}, bl1[2] = {l4[1], l4[3]};
#pragma unroll
                for (int mt = 0; mt < 2; mt++) {
                    mma16816(acc[mt][2 * np],     ah[mt], bh0);
                    mma16816(acc[mt][2 * np],     ah[mt], bl0);
                    mma16816(acc[mt][2 * np],     al[mt], bh0);
                    mma16816(acc[mt][2 * np + 1], ah[mt], bh1);
                    mma16816(acc[mt][2 * np + 1], ah[mt], bl1);
                    mma16816(acc[mt][2 * np + 1], al[mt], bh1);
                }
            }
        }
    }

    // Epilogue
#pragma unroll
    for (int mt = 0; mt < 2; mt++) {
#pragma unroll
        for (int nt = 0; nt < 8; nt++) {
            int r = row0 + wm + mt * 16 + (lane >> 2);
            int c = col0 + wn + nt * 8 + (lane & 3) * 2;
            if (Cf) {
                float b0 = 0.f, b1 = 0.f;
                if (bias) { b0 = bias[c]; b1 = bias[c + 1]; }
                float2 v0 = {acc[mt][nt][0] + b0, acc[mt][nt][1] + b1};
                float2 v1 = {acc[mt][nt][2] + b0, acc[mt][nt][3] + b1};
                *reinterpret_cast<float2*>(Cf + (size_t)r * Ncols + c)       = v0;
                *reinterpret_cast<float2*>(Cf + (size_t)(r + 8) * Ncols + c) = v1;
            } else {
                uint32_t h, l;
                pack_split(acc[mt][nt][0] * oscale, acc[mt][nt][1] * oscale, h, l);
                *reinterpret_cast<uint32_t*>(Ch + (size_t)r * Ncols + c) = h;
                *reinterpret_cast<uint32_t*>(Cl + (size_t)r * Ncols + c) = l;
                pack_split(acc[mt][nt][2] * oscale, acc[mt][nt][3] * oscale, h, l);
                *reinterpret_cast<uint32_t*>(Ch + (size_t)(r + 8) * Ncols + c) = h;
                *reinterpret_cast<uint32_t*>(Cl + (size_t)(r + 8) * Ncols + c) = l;
            }
        }
    }
}

// ---------------------------------------------------------------------------
// HMMA flash attention. CTA = 128 queries x one (b,h); 4 warps, each m32.
// Q pre-scaled by SCALE*LOG2E and split; K/V split. exp2-domain softmax.
// Key tiles: 32 full 64-key tiles + tile 32 = 3 memory tokens (padded).
// ---------------------------------------------------------------------------
#define AP 72

__global__ void __launch_bounds__(128) mma_attn_kernel(
    const __nv_bfloat16* __restrict__ qh, const __nv_bfloat16* __restrict__ ql,
    const __nv_bfloat16* __restrict__ kvh, const __nv_bfloat16* __restrict__ kvl,
    const float* __restrict__ mk, const float* __restrict__ mv,
    __nv_bfloat16* __restrict__ oh, __nv_bfloat16* __restrict__ ol)
{
    extern __shared__ __nv_bfloat16 sma[];
    // layout: sQh[128*AP] | sQl[128*AP] | sKh[64*AP] | sKl | sVh | sVl
    __nv_bfloat16* sQh = sma;
    __nv_bfloat16* sKh = sma + 2 * 128 * AP;
    const int tid = threadIdx.x, wid = tid >> 5, lane = tid & 31;
    const int bh = blockIdx.y, b = bh >> 3, h = bh & 7;
    const int q0 = blockIdx.x * 128;
    const int bN = b * NTOK;
    const uint32_t base = smem_u32(sma);
    const uint32_t offQl = 128 * AP * 2;
    const uint32_t offKh = 2 * 128 * AP * 2;
    const uint32_t offKl = offKh + 64 * AP * 2;
    const uint32_t offVh = offKl + 64 * AP * 2;
    const uint32_t offVl = offVh + 64 * AP * 2;

    // Load Q tile (bf16 hi/lo), 128x64
#pragma unroll
    for (int it = 0; it < 8; it++) {
        int i = tid + it * 128;        // 0..1023
        int r = i >> 3, u = i & 7;
        size_t go = (size_t)(bN + q0 + r) * DIMM + h * DHD + u * 8;
        *reinterpret_cast<uint4*>(sQh + r * AP + u * 8)            = *reinterpret_cast<const uint4*>(qh + go);
        *reinterpret_cast<uint4*>(sQh + 128 * AP + r * AP + u * 8) = *reinterpret_cast<const uint4*>(ql + go);
    }

    float o[2][8][4];
#pragma unroll
    for (int mt = 0; mt < 2; mt++)
#pragma unroll
        for (int nt = 0; nt < 8; nt++)
#pragma unroll
            for (int j = 0; j < 4; j++) o[mt][nt][j] = 0.0f;
    float mi[2][2] = {{-1e30f, -1e30f}, {-1e30f, -1e30f}};
    float li[2][2] = {{0.f, 0.f}, {0.f, 0.f}};

    const int lr = lane & 15, lc = (lane >> 4) * 8;

    for (int t = 0; t < 33; t++) {
        __syncthreads();
        if (t < 32) {
#pragma unroll
            for (int it = 0; it < 4; it++) {
                int i = tid + it * 128;     // 0..511
                int r = i >> 3, u = i & 7;
                size_t gk = (size_t)(bN + t * 64 + r) * (2 * DIMM) + h * DHD + u * 8;
                *reinterpret_cast<uint4*>(sKh + r * AP + u * 8)               = *reinterpret_cast<const uint4*>(kvh + gk);
                *reinterpret_cast<uint4*>(sKh + 64 * AP + r * AP + u * 8)     = *reinterpret_cast<const uint4*>(kvl + gk);
                *reinterpret_cast<uint4*>(sKh + 2 * 64 * AP + r * AP + u * 8) = *reinterpret_cast<const uint4*>(kvh + gk + DIMM);
                *reinterpret_cast<uint4*>(sKh + 3 * 64 * AP + r * AP + u * 8) = *reinterpret_cast<const uint4*>(kvl + gk + DIMM);
            }
        } else {
            uint4 z = {0u, 0u, 0u, 0u};
#pragma unroll
            for (int it = 0; it < 18; it++) {
                int i = tid + it * 128;     // 0..2303 over 4*64*AP elems
                *(reinterpret_cast<uint4*>(sKh) + i) = z;
            }
            __syncthreads();
            for (int idx = tid; idx < MTOK * 64; idx += 128) {
                int kk = idx >> 6, dd = idx & 63;
                int mi_ = h * (MTOK * DHD) + kk * DHD + dd;
                float kval = SQRT_DH * mk[mi_];
                float vval = SQRT_M  * mv[mi_];
                __nv_bfloat16 khh = __float2bfloat16(kval);
                sKh[kk * AP + dd]           = khh;
                sKh[64 * AP + kk * AP + dd] = __float2bfloat16(kval - __bfloat162float(khh));
                __nv_bfloat16 vhh = __float2bfloat16(vval);
                sKh[2 * 64 * AP + kk * AP + dd] = vhh;
                sKh[3 * 64 * AP + kk * AP + dd] = __float2bfloat16(vval - __bfloat162float(vhh));
            }
        }
        __syncthreads();

        // ---- S = Q K^T (m32 x n64 per warp) ----
        float s[2][8][4];
#pragma unroll
        for (int mt = 0; mt < 2; mt++)
#pragma unroll
            for (int nt = 0; nt < 8; nt++)
#pragma unroll
                for (int j = 0; j < 4; j++) s[mt][nt][j] = 0.0f;

#pragma unroll
        for (int kt = 0; kt < 4; kt++) {
            uint32_t ah[2][4], al[2][4];
#pragma unroll
            for (int mt = 0; mt < 2; mt++) {
                uint32_t ad = base + (uint32_t)(((wid * 32 + mt * 16 + lr) * AP + kt * 16 + lc) * 2);
                ldsm4(ah[mt], ad);
                ldsm4(al[mt], ad + offQl);
            }
#pragma unroll
            for (int np = 0; np < 4; np++) {
                uint32_t r4[4], l4[4];
                uint32_t kd = base + offKh + (uint32_t)(((np * 16 + lr) * AP + kt * 16 + lc) * 2);
                ldsm4(r4, kd);
                ldsm4(l4, kd + (offKl - offKh));
                uint32_t bh0[2] = {r4[0], r4[2]}, bh1[2] = {r4[1], r4[3]};
                uint32_t bl0[2] = {l4[0], l4[2]}, bl1[2] = {l4[1], l4[3]};
#pragma unroll
                for (int mt = 0; mt < 2; mt++) {
                    mma16816(s[mt][2 * np],     ah[mt], bh0);
                    mma16816(s[mt][2 * np],     ah[mt], bl0);
                    mma16816(s[mt][2 * np],     al[mt], bh0);
                    mma16816(s[mt][2 * np + 1], ah[mt], bh1);
                    mma16816(s[mt][2 * np + 1], ah[mt], bl1);
                    mma16816(s[mt][2 * np + 1], al[mt], bh1);
                }
            }
        }

        // ---- mask padded memory-token columns ----
        if (t == 32) {
#pragma unroll
            for (int nt = 0; nt < 8; nt++) {
                int c0 = nt * 8 + (lane & 3) * 2;
                if (c0 >= MTOK) {
#pragma unroll
                    for (int mt = 0; mt < 2; mt++) { s[mt][nt][0] = -1e30f; s[mt][nt][2] = -1e30f; }
                }
                if (c0 + 1 >= MTOK) {
#pragma unroll
                    for (int mt = 0; mt < 2; mt++) { s[mt][nt][1] = -1e30f; s[mt][nt][3] = -1e30f; }
                }
            }
        }

        // ---- online softmax (exp2 domain) ----
#pragma unroll
        for (int mt = 0; mt < 2; mt++) {
#pragma unroll
            for (int hh = 0; hh < 2; hh++) {
                float rm = -1e30f;
#pragma unroll
                for (int nt = 0; nt < 8; nt++) {
                    rm = fmaxf(rm, s[mt][nt][2 * hh]);
                    rm = fmaxf(rm, s[mt][nt][2 * hh + 1]);
                }
                rm = fmaxf(rm, __shfl_xor_sync(0xffffffffu, rm, 1));
                rm = fmaxf(rm, __shfl_xor_sync(0xffffffffu, rm, 2));
                float mn = fmaxf(mi[mt][hh], rm);
                float alpha = fast_exp2(mi[mt][hh] - mn);
                float sum = 0.f;
#pragma unroll
                for (int nt = 0; nt < 8; nt++) {
                    float p0 = fast_exp2(s[mt][nt][2 * hh]     - mn);
                    float p1 = fast_exp2(s[mt][nt][2 * hh + 1] - mn);
                    s[mt][nt][2 * hh]     = p0;
                    s[mt][nt][2 * hh + 1] = p1;
                    sum += p0 + p1;
                }
                sum += __shfl_xor_sync(0xffffffffu, sum, 1);
                sum += __shfl_xor_sync(0xffffffffu, sum, 2);
                li[mt][hh] = li[mt][hh] * alpha + sum;
                mi[mt][hh] = mn;
#pragma unroll
                for (int nt = 0; nt < 8; nt++) {
                    o[mt][nt][2 * hh]     *= alpha;
                    o[mt][nt][2 * hh + 1] *= alpha;
                }
            }
        }

        // ---- O += P V ----
#pragma unroll
        for (int kt = 0; kt < 4; kt++) {
            uint32_t vh[8][2], vl[8][2];
#pragma unroll
            for (int np = 0; np < 4; np++) {
                uint32_t r4[4], l4[4];
                uint32_t vd = base + offVh + (uint32_t)(((kt * 16 + lr) * AP + np * 16 + lc) * 2);
                ldsm4t(r4, vd);
                ldsm4t(l4, vd + (offVl - offVh));
                vh[2 * np][0] = r4[0]; vh[2 * np][1] = r4[1];
                vh[2 * np + 1][0] = r4[2]; vh[2 * np + 1][1] = r4[3];
                vl[2 * np][0] = l4[0]; vl[2 * np][1] = l4[1];
                vl[2 * np + 1][0] = l4[2]; vl[2 * np + 1][1] = l4[3];
            }
#pragma unroll
            for (int mt = 0; mt < 2; mt++) {
                uint32_t aph[4], apl[4];
                pack_split(s[mt][2 * kt][0],     s[mt][2 * kt][1],     aph[0], apl[0]);
                pack_split(s[mt][2 * kt][2],     s[mt][2 * kt][3],     aph[1], apl[1]);
                pack_split(s[mt][2 * kt + 1][0], s[mt][2 * kt + 1][1], aph[2], apl[2]);
                pack_split(s[mt][2 * kt + 1][2], s[mt][2 * kt + 1][3], aph[3], apl[3]);
#pragma unroll
                for (int nt = 0; nt < 8; nt++) {
                    mma16816(o[mt][nt], aph, vh[nt]);
                    mma16816(o[mt][nt], aph, vl[nt]);
                    mma16816(o[mt][nt], apl, vh[nt]);
                }
            }
        }
    }

    // ---- normalize + write bf16 hi/lo (feeds output projection) ----
    float inv[2][2];
#pragma unroll
    for (int mt = 0; mt < 2; mt++)
#pragma unroll
        for (int hh = 0; hh < 2; hh++) inv[mt][hh] = __fdividef(1.0f, li[mt][hh]);

#pragma unroll
    for (int mt = 0; mt < 2; mt++) {
#pragma unroll
        for (int nt = 0; nt < 8; nt++) {
            int r = q0 + wid * 32 + mt * 16 + (lane >> 2);
            int c = h * DHD + nt * 8 + (lane & 3) * 2;
            uint32_t ph, pl;
            pack_split(o[mt][nt][0] * inv[mt][0], o[mt][nt][1] * inv[mt][0], ph, pl);
            *reinterpret_cast<uint32_t*>(oh + (size_t)(bN + r) * DIMM + c) = ph;
            *reinterpret_cast<uint32_t*>(ol + (size_t)(bN + r) * DIMM + c) = pl;
            pack_split(o[mt][nt][2] * inv[mt][1], o[mt][nt][3] * inv[mt][1], ph, pl);
            *reinterpret_cast<uint32_t*>(oh + (size_t)(bN + r + 8) * DIMM + c) = ph;
            *reinterpret_cast<uint32_t*>(ol + (size_t)(bN + r + 8) * DIMM + c) = pl;
        }
    }
}

// ---------------------------------------------------------------------------
extern "C" void kernel_launch(void* const* d_in, const int* in_sizes, int n_in,
                              void* d_out, int out_size)
{
    const float* x   = (const float*)d_in[0];
    const float* wq  = (const float*)d_in[1];
    const float* wkv = (const float*)d_in[2];
    const float* wo  = (const float*)d_in[3];
    const float* bo  = (const float*)d_in[4];
    const float* m_k = (const float*)d_in[5];
    const float* m_v = (const float*)d_in[6];
    float* out = (float*)d_out;

    __nv_bfloat16 *xh, *xl, *qh, *ql, *kvh, *kvl, *ohp, *olp;
    __nv_bfloat16 *wqh, *wql, *wkvh, *wkvl, *woh, *wol;
    cudaGetSymbolAddress((void**)&xh,   g_xh);   cudaGetSymbolAddress((void**)&xl,   g_xl);
    cudaGetSymbolAddress((void**)&qh,   g_qh);   cudaGetSymbolAddress((void**)&ql,   g_ql);
    cudaGetSymbolAddress((void**)&kvh,  g_kvh);  cudaGetSymbolAddress((void**)&kvl,  g_kvl);
    cudaGetSymbolAddress((void**)&ohp,  g_oh);   cudaGetSymbolAddress((void**)&olp,  g_ol);
    cudaGetSymbolAddress((void**)&wqh,  g_wqh);  cudaGetSymbolAddress((void**)&wql,  g_wql);
    cudaGetSymbolAddress((void**)&wkvh, g_wkvh); cudaGetSymbolAddress((void**)&wkvl, g_wkvl);
    cudaGetSymbolAddress((void**)&woh,  g_woh);  cudaGetSymbolAddress((void**)&wol,  g_wol);

    const int GEMM_SMEM = 4 * 128 * GP * sizeof(__nv_bfloat16);           // 73728
    const int ATTN_SMEM = (2 * 128 * AP + 4 * 64 * AP) * sizeof(__nv_bfloat16); // 73728
    cudaFuncSetAttribute(mma_gemm_kernel, cudaFuncAttributeMaxDynamicSharedMemorySize, GEMM_SMEM);
    cudaFuncSetAttribute(mma_attn_kernel, cudaFuncAttributeMaxDynamicSharedMemorySize, ATTN_SMEM);

    // Prep: split inputs / transpose+split weights
    split_scale_kernel<<<(MROWS * KDIM / 4 + 255) / 256, 256>>>(x, xh, xl, MROWS * KDIM, 1.0f);
    transpose_split_kernel<<<(KDIM * DIMM + 255) / 256, 256>>>(wq, wqh, wql, KDIM, DIMM);
    transpose_split_kernel<<<(KDIM * 2 * DIMM + 255) / 256, 256>>>(wkv, wkvh, wkvl, KDIM, 2 * DIMM);
    transpose_split_kernel<<<(KDIM * DIMM + 255) / 256, 256>>>(wo, woh, wol, KDIM, DIMM);

    // Q projection -> bf16 hi/lo, pre-scaled by SCALE*LOG2E for exp2 softmax
    {
        dim3 grid(DIMM / 128, MROWS / 128);
        mma_gemm_kernel<<<grid, 256, GEMM_SMEM>>>(xh, xl, wqh, wql,
            nullptr, nullptr, qh, ql, SCALE * LOG2E, DIMM);
    }
    // KV projection -> bf16 hi/lo
    {
        dim3 grid(2 * DIMM / 128, MROWS / 128);
        mma_gemm_kernel<<<grid, 256, GEMM_SMEM>>>(xh, xl, wkvh, wkvl,
            nullptr, nullptr, kvh, kvl, 1.0f, 2 * DIMM);
    }
    // Attention -> bf16 hi/lo
    {
        dim3 grid(NTOK / 128, NB * NH);
        mma_attn_kernel<<<grid, 128, ATTN_SMEM>>>(qh, ql, kvh, kvl, m_k, m_v, ohp, olp);
    }
    // Output projection (+bias) -> fp32 out
    {
        dim3 grid(DIMM / 128, MROWS / 128);
        mma_gemm_kernel<<<grid, 256, GEMM_SMEM>>>(ohp, olp, woh, wol,
            out, bo, nullptr, nullptr, 1.0f, DIMM);
    }
}

// round 4
// speedup vs baseline: 3.1449x; 1.0626x over previous
#include <cuda_runtime.h>
#include <cuda_bf16.h>
#include <cstdint>

// Problem constants
#define NB    2
#define NTOK  2048
#define DIMM  512
#define NH    8
#define DHD   64
#define MTOK  3
#define SQRT_DH 8.0f
#define SQRT_M  1.7320508075688772f
#define SCALE   0.125f
#define LOG2E   1.4426950408889634f
#define QSCALE  (SCALE * LOG2E)
#define MROWS (NB * NTOK)   // 4096
#define KDIM  512

// ---------------------------------------------------------------------------
// Scratch (__device__ globals; no cudaMalloc allowed). All bf16 hi/lo pairs.
// ---------------------------------------------------------------------------
__device__ __nv_bfloat16 g_xh[MROWS * KDIM],      g_xl[MROWS * KDIM];
__device__ __nv_bfloat16 g_qh[MROWS * DIMM],      g_ql[MROWS * DIMM];
__device__ __nv_bfloat16 g_kvh[MROWS * 2 * DIMM], g_kvl[MROWS * 2 * DIMM];
__device__ __nv_bfloat16 g_oh[MROWS * DIMM],      g_ol[MROWS * DIMM];
__device__ __nv_bfloat16 g_w3h[3 * DIMM * KDIM],  g_w3l[3 * DIMM * KDIM]; // [wq|wkv]^T
__device__ __nv_bfloat16 g_woh[DIMM * KDIM],      g_wol[DIMM * KDIM];

// ---------------------------------------------------------------------------
// Warp-MMA primitives (generic sm_80+ PTX: ldmatrix + mma.sync bf16 + cp.async)
// ---------------------------------------------------------------------------
__device__ __forceinline__ uint32_t smem_u32(const void* p) {
    uint32_t a;
    asm("{ .reg .u64 t; cvta.to.shared.u64 t, %1; cvt.u32.u64 %0, t; }" : "=r"(a) : "l"(p));
    return a;
}
__device__ __forceinline__ void ldsm4(uint32_t* r, uint32_t a) {
    asm volatile("ldmatrix.sync.aligned.m8n8.x4.shared.b16 {%0,%1,%2,%3}, [%4];"
                 : "=r"(r[0]), "=r"(r[1]), "=r"(r[2]), "=r"(r[3]) : "r"(a));
}
__device__ __forceinline__ void ldsm4t(uint32_t* r, uint32_t a) {
    asm volatile("ldmatrix.sync.aligned.m8n8.x4.trans.shared.b16 {%0,%1,%2,%3}, [%4];"
                 : "=r"(r[0]), "=r"(r[1]), "=r"(r[2]), "=r"(r[3]) : "r"(a));
}
__device__ __forceinline__ void mma16816(float* c, const uint32_t* a, const uint32_t* b) {
    asm volatile(
        "mma.sync.aligned.m16n8k16.row.col.f32.bf16.bf16.f32 "
        "{%0,%1,%2,%3}, {%4,%5,%6,%7}, {%8,%9}, {%0,%1,%2,%3};"
        : "+f"(c[0]), "+f"(c[1]), "+f"(c[2]), "+f"(c[3])
        : "r"(a[0]), "r"(a[1]), "r"(a[2]), "r"(a[3]), "r"(b[0]), "r"(b[1]));
}
#define CP16(dst, src) \
    asm volatile("cp.async.cg.shared.global [%0], [%1], 16;" :: "r"(dst), "l"(src))
#define CP_COMMIT() asm volatile("cp.async.commit_group;" ::: "memory")
#define CP_WAIT0()  asm volatile("cp.async.wait_group 0;" ::: "memory")

__device__ __forceinline__ float fast_exp2(float x) {
    float r;
    asm("ex2.approx.f32 %0, %1;" : "=f"(r) : "f"(x));
    return r;
}
__device__ __forceinline__ void pack_split(float x, float y, uint32_t& h, uint32_t& l) {
    __nv_bfloat162 hh = __floats2bfloat162_rn(x, y);
    float2 hf = __bfloat1622float2(hh);
    __nv_bfloat162 ll = __floats2bfloat162_rn(x - hf.x, y - hf.y);
    h = reinterpret_cast<uint32_t&>(hh);
    l = reinterpret_cast<uint32_t&>(ll);
}

// ---------------------------------------------------------------------------
// Prep kernels
// ---------------------------------------------------------------------------
__global__ void __launch_bounds__(256) split_scale_kernel(
    const float* __restrict__ in, __nv_bfloat16* __restrict__ hi,
    __nv_bfloat16* __restrict__ lo, int n)
{
    int i = (blockIdx.x * 256 + threadIdx.x) * 4;
    if (i >= n) return;
    float4 v = *reinterpret_cast<const float4*>(in + i);
    uint32_t h0, l0, h1, l1;
    pack_split(v.x, v.y, h0, l0);
    pack_split(v.z, v.w, h1, l1);
    *reinterpret_cast<uint32_t*>(hi + i)     = h0;
    *reinterpret_cast<uint32_t*>(hi + i + 2) = h1;
    *reinterpret_cast<uint32_t*>(lo + i)     = l0;
    *reinterpret_cast<uint32_t*>(lo + i + 2) = l1;
}

// Tiled transpose+split: W[K][N] -> Th[rowOff+n][k], Tl (bf16 hi/lo, K=512 out stride)
__global__ void __launch_bounds__(256) transpose_split_tiled(
    const float* __restrict__ W, __nv_bfloat16* __restrict__ Th,
    __nv_bfloat16* __restrict__ Tl, int N, int rowOff)
{
    __shared__ float tile[32][33];
    const int tid = threadIdx.x;
    const int n0 = blockIdx.x * 32, k0 = blockIdx.y * 32;
#pragma unroll
    for (int it = 0; it < 4; it++) {
        int r = (tid >> 5) + it * 8;
        int c = tid & 31;
        tile[r][c] = W[(size_t)(k0 + r) * N + n0 + c];
    }
    __syncthreads();
    const int n = tid >> 3, kg = tid & 7;
    float v0 = tile[kg * 4 + 0][n], v1 = tile[kg * 4 + 1][n];
    float v2 = tile[kg * 4 + 2][n], v3 = tile[kg * 4 + 3][n];
    uint32_t h0, l0, h1, l1;
    pack_split(v0, v1, h0, l0);
    pack_split(v2, v3, h1, l1);
    size_t dst = (size_t)(rowOff + n0 + n) * KDIM + k0 + kg * 4;
    *reinterpret_cast<uint2*>(Th + dst) = make_uint2(h0, h1);
    *reinterpret_cast<uint2*>(Tl + dst) = make_uint2(l0, l1);
}

// ---------------------------------------------------------------------------
// HMMA GEMM (fused QKV variant + generic). CTA 128x128, 8 warps, BK=64.
// B pre-transposed [N][K]. mode: 0 = fused QKV (writes qh/ql w/ QSCALE for
// cols<512, kvh/kvl for cols>=512), 1 = fp32 out (+bias).
// ---------------------------------------------------------------------------
#define GP 72

__global__ void __launch_bounds__(256) mma_gemm_kernel(
    const __nv_bfloat16* __restrict__ Ah, const __nv_bfloat16* __restrict__ Al,
    const __nv_bfloat16* __restrict__ BTh, const __nv_bfloat16* __restrict__ BTl,
    float* __restrict__ Cf, const float* __restrict__ bias,
    __nv_bfloat16* __restrict__ Qh, __nv_bfloat16* __restrict__ Ql,
    __nv_bfloat16* __restrict__ KVh, __nv_bfloat16* __restrict__ KVl,
    int mode)
{
    extern __shared__ __nv_bfloat16 sm[];
    const int tid = threadIdx.x, wid = tid >> 5, lane = tid & 31;
    const int row0 = blockIdx.y * 128, col0 = blockIdx.x * 128;
    const int wm = (wid & 3) * 32, wn = (wid >> 2) * 64;
    const uint32_t base = smem_u32(sm);
    const uint32_t offAl = 128 * GP * 2, offBh = 2 * 128 * GP * 2, offBl = 3 * 128 * GP * 2;

    float acc[2][8][4];
#pragma unroll
    for (int mt = 0; mt < 2; mt++)
#pragma unroll
        for (int nt = 0; nt < 8; nt++)
#pragma unroll
            for (int j = 0; j < 4; j++) acc[mt][nt][j] = 0.0f;

    for (int chunk = 0; chunk < 8; chunk++) {
        int k0 = chunk * 64;
        __syncthreads();
#pragma unroll
        for (int it = 0; it < 4; it++) {
            int i = tid + it * 256;
            int r = i >> 3, u = i & 7;
            size_t ga = (size_t)(row0 + r) * KDIM + k0 + u * 8;
            size_t gb = (size_t)(col0 + r) * KDIM + k0 + u * 8;
            uint32_t d = base + (uint32_t)((r * GP + u * 8) * 2);
            CP16(d,         Ah + ga);
            CP16(d + offAl, Al + ga);
            CP16(d + offBh, BTh + gb);
            CP16(d + offBl, BTl + gb);
        }
        CP_COMMIT();
        CP_WAIT0();
        __syncthreads();

        const int lr = lane & 15, lc = (lane >> 4) * 8;
#pragma unroll
        for (int kt = 0; kt < 4; kt++) {
            uint32_t ah[2][4], al[2][4];
#pragma unroll
            for (int mt = 0; mt < 2; mt++) {
                uint32_t ad = base + (uint32_t)(((wm + mt * 16 + lr) * GP + kt * 16 + lc) * 2);
                ldsm4(ah[mt], ad);
                ldsm4(al[mt], ad + offAl);
            }
#pragma unroll
            for (int np = 0; np < 4; np++) {
                uint32_t r4[4], l4[4];
                uint32_t bd = base + offBh + (uint32_t)(((wn + np * 16 + lr) * GP + kt * 16 + lc) * 2);
                ldsm4(r4, bd);
                ldsm4(l4, bd + (offBl - offBh));
                uint32_t bh0[2] = {r4[0], r4[2]}, bh1[2] = {r4[1], r4[3]};
                uint32_t bl0[2] = {l4[0], l4[2]}, bl1[2] = {l4[1], l4[3]};
#pragma unroll
                for (int mt = 0; mt < 2; mt++) {
                    mma16816(acc[mt][2 * np],     ah[mt], bh0);
                    mma16816(acc[mt][2 * np],     ah[mt], bl0);
                    mma16816(acc[mt][2 * np],     al[mt], bh0);
                    mma16816(acc[mt][2 * np + 1], ah[mt], bh1);
                    mma16816(acc[mt][2 * np + 1], ah[mt], bl1);
                    mma16816(acc[mt][2 * np + 1], al[mt], bh1);
                }
            }
        }
    }

    // Epilogue
    if (mode == 1) {
#pragma unroll
        for (int mt = 0; mt < 2; mt++) {
#pragma unroll
            for (int nt = 0; nt < 8; nt++) {
                int r = row0 + wm + mt * 16 + (lane >> 2);
                int c = col0 + wn + nt * 8 + (lane & 3) * 2;
                float b0 = bias[c], b1 = bias[c + 1];
                float2 v0 = {acc[mt][nt][0] + b0, acc[mt][nt][1] + b1};
                float2 v1 = {acc[mt][nt][2] + b0, acc[mt][nt][3] + b1};
                *reinterpret_cast<float2*>(Cf + (size_t)r * DIMM + c)       = v0;
                *reinterpret_cast<float2*>(Cf + (size_t)(r + 8) * DIMM + c) = v1;
            }
        }
    } else {
        const bool isq = (col0 < DIMM);
        __nv_bfloat16* Ch = isq ? Qh : KVh;
        __nv_bfloat16* Cl = isq ? Ql : KVl;
        const int ncol  = isq ? DIMM : 2 * DIMM;
        const int cbase = isq ? col0 : col0 - DIMM;
        const float osc = isq ? QSCALE : 1.0f;
#pragma unroll
        for (int mt = 0; mt < 2; mt++) {
#pragma unroll
            for (int nt = 0; nt < 8; nt++) {
                int r = row0 + wm + mt * 16 + (lane >> 2);
                int c = cbase + wn + nt * 8 + (lane & 3) * 2;
                uint32_t h, l;
                pack_split(acc[mt][nt][0] * osc, acc[mt][nt][1] * osc, h, l);
                *reinterpret_cast<uint32_t*>(Ch + (size_t)r * ncol + c) = h;
                *reinterpret_cast<uint32_t*>(Cl + (size_t)r * ncol + c) = l;
                pack_split(acc[mt][nt][2] * osc, acc[mt][nt][3] * osc, h, l);
                *reinterpret_cast<uint32_t*>(Ch + (size_t)(r + 8) * ncol + c) = h;
                *reinterpret_cast<uint32_t*>(Cl + (size_t)(r + 8) * ncol + c) = l;
            }
        }
    }
}

// ---------------------------------------------------------------------------
// HMMA flash attention with cp.async double-buffered K/V pipeline.
// CTA = 128 queries x one (b,h); 4 warps (m32 each). exp2-domain softmax.
// Tiles 0..31 = 64 keys each (pipelined); tile 32 = 3 memory tokens.
// ---------------------------------------------------------------------------
#define AP 72
#define KVSTAGE_B (4 * 64 * AP * 2)  // 36864 bytes per stage

__global__ void __launch_bounds__(128) mma_attn_kernel(
    const __nv_bfloat16* __restrict__ qh, const __nv_bfloat16* __restrict__ ql,
    const __nv_bfloat16* __restrict__ kvh, const __nv_bfloat16* __restrict__ kvl,
    const float* __restrict__ mk, const float* __restrict__ mv,
    __nv_bfloat16* __restrict__ oh, __nv_bfloat16* __restrict__ ol)
{
    extern __shared__ __nv_bfloat16 sma[];
    // layout: Qh[128*AP] | Ql[128*AP] | stage0{Kh,Kl,Vh,Vl each 64*AP} | stage1{...}
    const int tid = threadIdx.x, wid = tid >> 5, lane = tid & 31;
    const int bh = blockIdx.y, b = bh >> 3, h = bh & 7;
    const int q0 = blockIdx.x * 128;
    const int bN = b * NTOK;
    const uint32_t base = smem_u32(sma);
    const uint32_t offQl = 128 * AP * 2;
    const uint32_t offKV = 2 * 128 * AP * 2;   // 36864

    // Load Q tile (bf16 hi/lo), 128x64
#pragma unroll
    for (int it = 0; it < 8; it++) {
        int i = tid + it * 128;
        int r = i >> 3, u = i & 7;
        size_t go = (size_t)(bN + q0 + r) * DIMM + h * DHD + u * 8;
        *reinterpret_cast<uint4*>(sma + r * AP + u * 8)            = *reinterpret_cast<const uint4*>(qh + go);
        *reinterpret_cast<uint4*>(sma + 128 * AP + r * AP + u * 8) = *reinterpret_cast<const uint4*>(ql + go);
    }

    float o[2][8][4];
#pragma unroll
    for (int mt = 0; mt < 2; mt++)
#pragma unroll
        for (int nt = 0; nt < 8; nt++)
#pragma unroll
            for (int j = 0; j < 4; j++) o[mt][nt][j] = 0.0f;
    float mi[2][2] = {{-1e30f, -1e30f}, {-1e30f, -1e30f}};
    float li[2][2] = {{0.f, 0.f}, {0.f, 0.f}};

    const int lr = lane & 15, lc = (lane >> 4) * 8;

    // Prologue: prefetch tile 0 into stage 0
    {
        const uint32_t kb = base + offKV;
#pragma unroll
        for (int it = 0; it < 4; it++) {
            int i = tid + it * 128;
            int r = i >> 3, u = i & 7;
            size_t gk = (size_t)(bN + r) * (2 * DIMM) + h * DHD + u * 8;
            uint32_t d = kb + (uint32_t)((r * AP + u * 8) * 2);
            CP16(d,         kvh + gk);
            CP16(d + 9216,  kvl + gk);
            CP16(d + 18432, kvh + gk + DIMM);
            CP16(d + 27648, kvl + gk + DIMM);
        }
        CP_COMMIT();
    }

    for (int t = 0; t < 33; t++) {
        const int stage = t & 1;
        const uint32_t kb = base + offKV + stage * KVSTAGE_B;

        if (t < 32) CP_WAIT0();
        __syncthreads();

        if (t + 1 < 32) {
            const uint32_t kb2 = base + offKV + (stage ^ 1) * KVSTAGE_B;
#pragma unroll
            for (int it = 0; it < 4; it++) {
                int i = tid + it * 128;
                int r = i >> 3, u = i & 7;
                size_t gk = (size_t)(bN + (t + 1) * 64 + r) * (2 * DIMM) + h * DHD + u * 8;
                uint32_t d = kb2 + (uint32_t)((r * AP + u * 8) * 2);
                CP16(d,         kvh + gk);
                CP16(d + 9216,  kvl + gk);
                CP16(d + 18432, kvh + gk + DIMM);
                CP16(d + 27648, kvl + gk + DIMM);
            }
            CP_COMMIT();
        }

        if (t == 32) {
            // zero the stage-0 KV region, then fill 3 memory tokens
            __nv_bfloat16* skv = sma + 2 * 128 * AP;  // stage 0
            uint4 z = {0u, 0u, 0u, 0u};
#pragma unroll
            for (int it = 0; it < 18; it++)
                *(reinterpret_cast<uint4*>(skv) + tid + it * 128) = z;
            __syncthreads();
            for (int idx = tid; idx < MTOK * 64; idx += 128) {
                int kk = idx >> 6, dd = idx & 63;
                int mi_ = h * (MTOK * DHD) + kk * DHD + dd;
                float kval = SQRT_DH * mk[mi_];
                float vval = SQRT_M  * mv[mi_];
                __nv_bfloat16 khh = __float2bfloat16(kval);
                skv[kk * AP + dd]           = khh;
                skv[64 * AP + kk * AP + dd] = __float2bfloat16(kval - __bfloat162float(khh));
                __nv_bfloat16 vhh = __float2bfloat16(vval);
                skv[2 * 64 * AP + kk * AP + dd] = vhh;
                skv[3 * 64 * AP + kk * AP + dd] = __float2bfloat16(vval - __bfloat162float(vhh));
            }
            __syncthreads();
        }
        const uint32_t kbc = (t == 32) ? (base + offKV) : kb;

        // ---- S = Q K^T ----
        float s[2][8][4];
#pragma unroll
        for (int mt = 0; mt < 2; mt++)
#pragma unroll
            for (int nt = 0; nt < 8; nt++)
#pragma unroll
                for (int j = 0; j < 4; j++) s[mt][nt][j] = 0.0f;

#pragma unroll
        for (int kt = 0; kt < 4; kt++) {
            uint32_t ah[2][4], al[2][4];
#pragma unroll
            for (int mt = 0; mt < 2; mt++) {
                uint32_t ad = base + (uint32_t)(((wid * 32 + mt * 16 + lr) * AP + kt * 16 + lc) * 2);
                ldsm4(ah[mt], ad);
                ldsm4(al[mt], ad + offQl);
            }
#pragma unroll
            for (int np = 0; np < 4; np++) {
                uint32_t r4[4], l4[4];
                uint32_t kd = kbc + (uint32_t)(((np * 16 + lr) * AP + kt * 16 + lc) * 2);
                ldsm4(r4, kd);
                ldsm4(l4, kd + 9216);
                uint32_t bh0[2] = {r4[0], r4[2]}, bh1[2] = {r4[1], r4[3]};
                uint32_t bl0[2] = {l4[0], l4[2]}, bl1[2] = {l4[1], l4[3]};
#pragma unroll
                for (int mt = 0; mt < 2; mt++) {
                    mma16816(s[mt][2 * np],     ah[mt], bh0);
                    mma16816(s[mt][2 * np],     ah[mt], bl0);
                    mma16816(s[mt][2 * np],     al[mt], bh0);
                    mma16816(s[mt][2 * np + 1], ah[mt], bh1);
                    mma16816(s[mt][2 * np + 1], ah[mt], bl1);
                    mma16816(s[mt][2 * np + 1], al[mt], bh1);
                }
            }
        }

        if (t == 32) {
#pragma unroll
            for (int nt = 0; nt < 8; nt++) {
                int c0 = nt * 8 + (lane & 3) * 2;
                if (c0 >= MTOK) {
#pragma unroll
                    for (int mt = 0; mt < 2; mt++) { s[mt][nt][0] = -1e30f; s[mt][nt][2] = -1e30f; }
                }
                if (c0 + 1 >= MTOK) {
#pragma unroll
                    for (int mt = 0; mt < 2; mt++) { s[mt][nt][1] = -1e30f; s[mt][nt][3] = -1e30f; }
                }
            }
        }

        // ---- online softmax (exp2 domain) ----
#pragma unroll
        for (int mt = 0; mt < 2; mt++) {
#pragma unroll
            for (int hh = 0; hh < 2; hh++) {
                float rm = -1e30f;
#pragma unroll
                for (int nt = 0; nt < 8; nt++) {
                    rm = fmaxf(rm, s[mt][nt][2 * hh]);
                    rm = fmaxf(rm, s[mt][nt][2 * hh + 1]);
                }
                rm = fmaxf(rm, __shfl_xor_sync(0xffffffffu, rm, 1));
                rm = fmaxf(rm, __shfl_xor_sync(0xffffffffu, rm, 2));
                float mn = fmaxf(mi[mt][hh], rm);
                float alpha = fast_exp2(mi[mt][hh] - mn);
                float sum = 0.f;
#pragma unroll
                for (int nt = 0; nt < 8; nt++) {
                    float p0 = fast_exp2(s[mt][nt][2 * hh]     - mn);
                    float p1 = fast_exp2(s[mt][nt][2 * hh + 1] - mn);
                    s[mt][nt][2 * hh]     = p0;
                    s[mt][nt][2 * hh + 1] = p1;
                    sum += p0 + p1;
                }
                sum += __shfl_xor_sync(0xffffffffu, sum, 1);
                sum += __shfl_xor_sync(0xffffffffu, sum, 2);
                li[mt][hh] = li[mt][hh] * alpha + sum;
                mi[mt][hh] = mn;
#pragma unroll
                for (int nt = 0; nt < 8; nt++) {
                    o[mt][nt][2 * hh]     *= alpha;
                    o[mt][nt][2 * hh + 1] *= alpha;
                }
            }
        }

        // ---- O += P V ----
#pragma unroll
        for (int kt = 0; kt < 4; kt++) {
            uint32_t vh[8][2], vl[8][2];
#pragma unroll
            for (int np = 0; np < 4; np++) {
                uint32_t r4[4], l4[4];
                uint32_t vd = kbc + 18432 + (uint32_t)(((kt * 16 + lr) * AP + np * 16 + lc) * 2);
                ldsm4t(r4, vd);
                ldsm4t(l4, vd + 9216);
                vh[2 * np][0] = r4[0]; vh[2 * np][1] = r4[1];
                vh[2 * np + 1][0] = r4[2]; vh[2 * np + 1][1] = r4[3];
                vl[2 * np][0] = l4[0]; vl[2 * np][1] = l4[1];
                vl[2 * np + 1][0] = l4[2]; vl[2 * np + 1][1] = l4[3];
            }
#pragma unroll
            for (int mt = 0; mt < 2; mt++) {
                uint32_t aph[4], apl[4];
                pack_split(s[mt][2 * kt][0],     s[mt][2 * kt][1],     aph[0], apl[0]);
                pack_split(s[mt][2 * kt][2],     s[mt][2 * kt][3],     aph[1], apl[1]);
                pack_split(s[mt][2 * kt + 1][0], s[mt][2 * kt + 1][1], aph[2], apl[2]);
                pack_split(s[mt][2 * kt + 1][2], s[mt][2 * kt + 1][3], aph[3], apl[3]);
#pragma unroll
                for (int nt = 0; nt < 8; nt++) {
                    mma16816(o[mt][nt], aph, vh[nt]);
                    mma16816(o[mt][nt], aph, vl[nt]);
                    mma16816(o[mt][nt], apl, vh[nt]);
                }
            }
        }
    }

    // ---- normalize + write bf16 hi/lo ----
    float inv[2][2];
#pragma unroll
    for (int mt = 0; mt < 2; mt++)
#pragma unroll
        for (int hh = 0; hh < 2; hh++) inv[mt][hh] = __fdividef(1.0f, li[mt][hh]);

#pragma unroll
    for (int mt = 0; mt < 2; mt++) {
#pragma unroll
        for (int nt = 0; nt < 8; nt++) {
            int r = q0 + wid * 32 + mt * 16 + (lane >> 2);
            int c = h * DHD + nt * 8 + (lane & 3) * 2;
            uint32_t ph, pl;
            pack_split(o[mt][nt][0] * inv[mt][0], o[mt][nt][1] * inv[mt][0], ph, pl);
            *reinterpret_cast<uint32_t*>(oh + (size_t)(bN + r) * DIMM + c) = ph;
            *reinterpret_cast<uint32_t*>(ol + (size_t)(bN + r) * DIMM + c) = pl;
            pack_split(o[mt][nt][2] * inv[mt][1], o[mt][nt][3] * inv[mt][1], ph, pl);
            *reinterpret_cast<uint32_t*>(oh + (size_t)(bN + r + 8) * DIMM + c) = ph;
            *reinterpret_cast<uint32_t*>(ol + (size_t)(bN + r + 8) * DIMM + c) = pl;
        }
    }
}

// ---------------------------------------------------------------------------
extern "C" void kernel_launch(void* const* d_in, const int* in_sizes, int n_in,
                              void* d_out, int out_size)
{
    const float* x   = (const float*)d_in[0];
    const float* wq  = (const float*)d_in[1];
    const float* wkv = (const float*)d_in[2];
    const float* wo  = (const float*)d_in[3];
    const float* bo  = (const float*)d_in[4];
    const float* m_k = (const float*)d_in[5];
    const float* m_v = (const float*)d_in[6];
    float* out = (float*)d_out;

    __nv_bfloat16 *xh, *xl, *qh, *ql, *kvh, *kvl, *ohp, *olp;
    __nv_bfloat16 *w3h, *w3l, *woh, *wol;
    cudaGetSymbolAddress((void**)&xh,   g_xh);   cudaGetSymbolAddress((void**)&xl,   g_xl);
    cudaGetSymbolAddress((void**)&qh,   g_qh);   cudaGetSymbolAddress((void**)&ql,   g_ql);
    cudaGetSymbolAddress((void**)&kvh,  g_kvh);  cudaGetSymbolAddress((void**)&kvl,  g_kvl);
    cudaGetSymbolAddress((void**)&ohp,  g_oh);   cudaGetSymbolAddress((void**)&olp,  g_ol);
    cudaGetSymbolAddress((void**)&w3h,  g_w3h);  cudaGetSymbolAddress((void**)&w3l,  g_w3l);
    cudaGetSymbolAddress((void**)&woh,  g_woh);  cudaGetSymbolAddress((void**)&wol,  g_wol);

    const int GEMM_SMEM = 4 * 128 * GP * sizeof(__nv_bfloat16);                      // 73728
    const int ATTN_SMEM = (2 * 128 * AP) * (int)sizeof(__nv_bfloat16) + 2 * KVSTAGE_B; // 110592
    cudaFuncSetAttribute(mma_gemm_kernel, cudaFuncAttributeMaxDynamicSharedMemorySize, GEMM_SMEM);
    cudaFuncSetAttribute(mma_attn_kernel, cudaFuncAttributeMaxDynamicSharedMemorySize, ATTN_SMEM);

    // Prep: split x; transpose+split weights into combined [wq|wkv]^T and wo^T
    split_scale_kernel<<<(MROWS * KDIM / 4 + 255) / 256, 256>>>(x, xh, xl, MROWS * KDIM);
    {
        dim3 gq(DIMM / 32, KDIM / 32);
        transpose_split_tiled<<<gq, 256>>>(wq, w3h, w3l, DIMM, 0);
        dim3 gkv(2 * DIMM / 32, KDIM / 32);
        transpose_split_tiled<<<gkv, 256>>>(wkv, w3h, w3l, 2 * DIMM, DIMM);
        dim3 go(DIMM / 32, KDIM / 32);
        transpose_split_tiled<<<go, 256>>>(wo, woh, wol, DIMM, 0);
    }

    // Fused Q+KV projection (N=1536)
    {
        dim3 grid(3 * DIMM / 128, MROWS / 128);
        mma_gemm_kernel<<<grid, 256, GEMM_SMEM>>>(xh, xl, w3h, w3l,
            nullptr, nullptr, qh, ql, kvh, kvl, 0);
    }
    // Attention
    {
        dim3 grid(NTOK / 128, NB * NH);
        mma_attn_kernel<<<grid, 128, ATTN_SMEM>>>(qh, ql, kvh, kvl, m_k, m_v, ohp, olp);
    }
    // Output projection (+bias) -> fp32
    {
        dim3 grid(DIMM / 128, MROWS / 128);
        mma_gemm_kernel<<<grid, 256, GEMM_SMEM>>>(ohp, olp, woh, wol,
            out, bo, nullptr, nullptr, nullptr, nullptr, 1);
    }
}

// round 5
// speedup vs baseline: 3.1584x; 1.0043x over previous
#include <cuda_runtime.h>
#include <cuda_bf16.h>
#include <cstdint>

// Problem constants
#define NB    2
#define NTOK  2048
#define DIMM  512
#define NH    8
#define DHD   64
#define MTOK  3
#define SQRT_DH 8.0f
#define SQRT_M  1.7320508075688772f
#define SCALE   0.125f
#define LOG2E   1.4426950408889634f
#define QSCALE  (SCALE * LOG2E)
#define MROWS (NB * NTOK)   // 4096
#define KDIM  512

// ---------------------------------------------------------------------------
// Scratch (__device__ globals)
// ---------------------------------------------------------------------------
__device__ __nv_bfloat16 g_xh[MROWS * KDIM],      g_xl[MROWS * KDIM];
__device__ __nv_bfloat16 g_qh[MROWS * DIMM],      g_ql[MROWS * DIMM];
__device__ __nv_bfloat16 g_kvh[MROWS * 2 * DIMM], g_kvl[MROWS * 2 * DIMM];
__device__ __nv_bfloat16 g_oh[MROWS * DIMM],      g_ol[MROWS * DIMM];
__device__ __nv_bfloat16 g_w3h[3 * DIMM * KDIM],  g_w3l[3 * DIMM * KDIM]; // [wq|wkv]^T
__device__ __nv_bfloat16 g_woh[DIMM * KDIM],      g_wol[DIMM * KDIM];

// ---------------------------------------------------------------------------
// Warp-MMA primitives (generic sm_80+ PTX)
// ---------------------------------------------------------------------------
__device__ __forceinline__ uint32_t smem_u32(const void* p) {
    uint32_t a;
    asm("{ .reg .u64 t; cvta.to.shared.u64 t, %1; cvt.u32.u64 %0, t; }" : "=r"(a) : "l"(p));
    return a;
}
__device__ __forceinline__ void ldsm4(uint32_t* r, uint32_t a) {
    asm volatile("ldmatrix.sync.aligned.m8n8.x4.shared.b16 {%0,%1,%2,%3}, [%4];"
                 : "=r"(r[0]), "=r"(r[1]), "=r"(r[2]), "=r"(r[3]) : "r"(a));
}
__device__ __forceinline__ void ldsm4t(uint32_t* r, uint32_t a) {
    asm volatile("ldmatrix.sync.aligned.m8n8.x4.trans.shared.b16 {%0,%1,%2,%3}, [%4];"
                 : "=r"(r[0]), "=r"(r[1]), "=r"(r[2]), "=r"(r[3]) : "r"(a));
}
__device__ __forceinline__ void mma16816(float* c, const uint32_t* a, const uint32_t* b) {
    asm volatile(
        "mma.sync.aligned.m16n8k16.row.col.f32.bf16.bf16.f32 "
        "{%0,%1,%2,%3}, {%4,%5,%6,%7}, {%8,%9}, {%0,%1,%2,%3};"
        : "+f"(c[0]), "+f"(c[1]), "+f"(c[2]), "+f"(c[3])
        : "r"(a[0]), "r"(a[1]), "r"(a[2]), "r"(a[3]), "r"(b[0]), "r"(b[1]));
}
#define CP16(dst, src) \
    asm volatile("cp.async.cg.shared.global [%0], [%1], 16;" :: "r"(dst), "l"(src))
#define CP_COMMIT() asm volatile("cp.async.commit_group;" ::: "memory")
#define CP_WAIT0()  asm volatile("cp.async.wait_group 0;" ::: "memory")

__device__ __forceinline__ float fast_exp2(float x) {
    float r;
    asm("ex2.approx.f32 %0, %1;" : "=f"(r) : "f"(x));
    return r;
}
__device__ __forceinline__ void pack_split(float x, float y, uint32_t& h, uint32_t& l) {
    __nv_bfloat162 hh = __floats2bfloat162_rn(x, y);
    float2 hf = __bfloat1622float2(hh);
    __nv_bfloat162 ll = __floats2bfloat162_rn(x - hf.x, y - hf.y);
    h = reinterpret_cast<uint32_t&>(hh);
    l = reinterpret_cast<uint32_t&>(ll);
}

// ---------------------------------------------------------------------------
// Prep kernels
// ---------------------------------------------------------------------------
__global__ void __launch_bounds__(256) split_scale_kernel(
    const float* __restrict__ in, __nv_bfloat16* __restrict__ hi,
    __nv_bfloat16* __restrict__ lo, int n)
{
    int i = (blockIdx.x * 256 + threadIdx.x) * 4;
    if (i >= n) return;
    float4 v = *reinterpret_cast<const float4*>(in + i);
    uint32_t h0, l0, h1, l1;
    pack_split(v.x, v.y, h0, l0);
    pack_split(v.z, v.w, h1, l1);
    *reinterpret_cast<uint32_t*>(hi + i)     = h0;
    *reinterpret_cast<uint32_t*>(hi + i + 2) = h1;
    *reinterpret_cast<uint32_t*>(lo + i)     = l0;
    *reinterpret_cast<uint32_t*>(lo + i + 2) = l1;
}

// One launch: transpose+split wq (N=512), wkv (N=1024), wo (N=512).
// 64x64 fp32 tiles, 256 threads. Column-tile index ct selects source.
__global__ void __launch_bounds__(256) transpose_split_all(
    const float* __restrict__ wq, const float* __restrict__ wkv,
    const float* __restrict__ wo,
    __nv_bfloat16* __restrict__ w3h, __nv_bfloat16* __restrict__ w3l,
    __nv_bfloat16* __restrict__ woh, __nv_bfloat16* __restrict__ wol)
{
    __shared__ float tile[64][65];
    const int tid = threadIdx.x;
    const int ct = blockIdx.x;       // 0..31
    const int k0 = blockIdx.y * 64;

    const float* src;
    __nv_bfloat16 *dh, *dl;
    int N, n0, rowOff;
    if (ct < 8)       { src = wq;  N = 512;  n0 = ct * 64;        dh = w3h; dl = w3l; rowOff = 0; }
    else if (ct < 24) { src = wkv; N = 1024; n0 = (ct - 8) * 64;  dh = w3h; dl = w3l; rowOff = DIMM; }
    else              { src = wo;  N = 512;  n0 = (ct - 24) * 64; dh = woh; dl = wol; rowOff = 0; }

#pragma unroll
    for (int it = 0; it < 4; it++) {
        int idx = tid + it * 256;         // 0..1023
        int r = idx >> 4, c4 = (idx & 15) * 4;
        float4 v = *reinterpret_cast<const float4*>(src + (size_t)(k0 + r) * N + n0 + c4);
        tile[r][c4 + 0] = v.x; tile[r][c4 + 1] = v.y;
        tile[r][c4 + 2] = v.z; tile[r][c4 + 3] = v.w;
    }
    __syncthreads();
#pragma unroll
    for (int it = 0; it < 4; it++) {
        int idx = tid + it * 256;         // 0..1023
        int n = idx >> 4, kg = idx & 15;
        float v0 = tile[kg * 4 + 0][n], v1 = tile[kg * 4 + 1][n];
        float v2 = tile[kg * 4 + 2][n], v3 = tile[kg * 4 + 3][n];
        uint32_t h0, l0, h1, l1;
        pack_split(v0, v1, h0, l0);
        pack_split(v2, v3, h1, l1);
        size_t dst = (size_t)(rowOff + n0 + n) * KDIM + k0 + kg * 4;
        *reinterpret_cast<uint2*>(dh + dst) = make_uint2(h0, h1);
        *reinterpret_cast<uint2*>(dl + dst) = make_uint2(l0, l1);
    }
}

// ---------------------------------------------------------------------------
// HMMA GEMM (fused QKV / fp32+bias). CTA 128x128, 8 warps, BK=64.
// ---------------------------------------------------------------------------
#define GP 72

__global__ void __launch_bounds__(256) mma_gemm_kernel(
    const __nv_bfloat16* __restrict__ Ah, const __nv_bfloat16* __restrict__ Al,
    const __nv_bfloat16* __restrict__ BTh, const __nv_bfloat16* __restrict__ BTl,
    float* __restrict__ Cf, const float* __restrict__ bias,
    __nv_bfloat16* __restrict__ Qh, __nv_bfloat16* __restrict__ Ql,
    __nv_bfloat16* __restrict__ KVh, __nv_bfloat16* __restrict__ KVl,
    int mode)
{
    extern __shared__ __nv_bfloat16 sm[];
    const int tid = threadIdx.x, wid = tid >> 5, lane = tid & 31;
    const int row0 = blockIdx.y * 128, col0 = blockIdx.x * 128;
    const int wm = (wid & 3) * 32, wn = (wid >> 2) * 64;
    const uint32_t base = smem_u32(sm);
    const uint32_t offAl = 128 * GP * 2, offBh = 2 * 128 * GP * 2, offBl = 3 * 128 * GP * 2;

    float acc[2][8][4];
#pragma unroll
    for (int mt = 0; mt < 2; mt++)
#pragma unroll
        for (int nt = 0; nt < 8; nt++)
#pragma unroll
            for (int j = 0; j < 4; j++) acc[mt][nt][j] = 0.0f;

    for (int chunk = 0; chunk < 8; chunk++) {
        int k0 = chunk * 64;
        __syncthreads();
#pragma unroll
        for (int it = 0; it < 4; it++) {
            int i = tid + it * 256;
            int r = i >> 3, u = i & 7;
            size_t ga = (size_t)(row0 + r) * KDIM + k0 + u * 8;
            size_t gb = (size_t)(col0 + r) * KDIM + k0 + u * 8;
            uint32_t d = base + (uint32_t)((r * GP + u * 8) * 2);
            CP16(d,         Ah + ga);
            CP16(d + offAl, Al + ga);
            CP16(d + offBh, BTh + gb);
            CP16(d + offBl, BTl + gb);
        }
        CP_COMMIT();
        CP_WAIT0();
        __syncthreads();

        const int lr = lane & 15, lc = (lane >> 4) * 8;
#pragma unroll
        for (int kt = 0; kt < 4; kt++) {
            uint32_t ah[2][4], al[2][4];
#pragma unroll
            for (int mt = 0; mt < 2; mt++) {
                uint32_t ad = base + (uint32_t)(((wm + mt * 16 + lr) * GP + kt * 16 + lc) * 2);
                ldsm4(ah[mt], ad);
                ldsm4(al[mt], ad + offAl);
            }
#pragma unroll
            for (int np = 0; np < 4; np++) {
                uint32_t r4[4], l4[4];
                uint32_t bd = base + offBh + (uint32_t)(((wn + np * 16 + lr) * GP + kt * 16 + lc) * 2);
                ldsm4(r4, bd);
                ldsm4(l4, bd + (offBl - offBh));
                uint32_t bh0[2] = {r4[0], r4[2]}, bh1[2] = {r4[1], r4[3]};
                uint32_t bl0[2] = {l4[0], l4[2]}, bl1[2] = {l4[1], l4[3]};
#pragma unroll
                for (int mt = 0; mt < 2; mt++) {
                    mma16816(acc[mt][2 * np],     ah[mt], bh0);
                    mma16816(acc[mt][2 * np],     ah[mt], bl0);
                    mma16816(acc[mt][2 * np],     al[mt], bh0);
                    mma16816(acc[mt][2 * np + 1], ah[mt], bh1);
                    mma16816(acc[mt][2 * np + 1], ah[mt], bl1);
                    mma16816(acc[mt][2 * np + 1], al[mt], bh1);
                }
            }
        }
    }

    if (mode == 1) {
#pragma unroll
        for (int mt = 0; mt < 2; mt++) {
#pragma unroll
            for (int nt = 0; nt < 8; nt++) {
                int r = row0 + wm + mt * 16 + (lane >> 2);
                int c = col0 + wn + nt * 8 + (lane & 3) * 2;
                float b0 = bias[c], b1 = bias[c + 1];
                float2 v0 = {acc[mt][nt][0] + b0, acc[mt][nt][1] + b1};
                float2 v1 = {acc[mt][nt][2] + b0, acc[mt][nt][3] + b1};
                *reinterpret_cast<float2*>(Cf + (size_t)r * DIMM + c)       = v0;
                *reinterpret_cast<float2*>(Cf + (size_t)(r + 8) * DIMM + c) = v1;
            }
        }
    } else {
        const bool isq = (col0 < DIMM);
        __nv_bfloat16* Ch = isq ? Qh : KVh;
        __nv_bfloat16* Cl = isq ? Ql : KVl;
        const int ncol  = isq ? DIMM : 2 * DIMM;
        const int cbase = isq ? col0 : col0 - DIMM;
        const float osc = isq ? QSCALE : 1.0f;
#pragma unroll
        for (int mt = 0; mt < 2; mt++) {
#pragma unroll
            for (int nt = 0; nt < 8; nt++) {
                int r = row0 + wm + mt * 16 + (lane >> 2);
                int c = cbase + wn + nt * 8 + (lane & 3) * 2;
                uint32_t h, l;
                pack_split(acc[mt][nt][0] * osc, acc[mt][nt][1] * osc, h, l);
                *reinterpret_cast<uint32_t*>(Ch + (size_t)r * ncol + c) = h;
                *reinterpret_cast<uint32_t*>(Cl + (size_t)r * ncol + c) = l;
                pack_split(acc[mt][nt][2] * osc, acc[mt][nt][3] * osc, h, l);
                *reinterpret_cast<uint32_t*>(Ch + (size_t)(r + 8) * ncol + c) = h;
                *reinterpret_cast<uint32_t*>(Cl + (size_t)(r + 8) * ncol + c) = l;
            }
        }
    }
}

// ---------------------------------------------------------------------------
// HMMA flash attention, 8 warps (m16 each), cp.async double-buffered K/V.
// CTA = 128 queries x one (b,h). exp2-domain softmax.
// ---------------------------------------------------------------------------
#define AP 72
#define KVSTAGE_B (4 * 64 * AP * 2)  // 36864 bytes per stage

__global__ void __launch_bounds__(256, 2) mma_attn_kernel(
    const __nv_bfloat16* __restrict__ qh, const __nv_bfloat16* __restrict__ ql,
    const __nv_bfloat16* __restrict__ kvh, const __nv_bfloat16* __restrict__ kvl,
    const float* __restrict__ mk, const float* __restrict__ mv,
    __nv_bfloat16* __restrict__ oh, __nv_bfloat16* __restrict__ ol)
{
    extern __shared__ __nv_bfloat16 sma[];
    // layout: Qh[128*AP] | Ql[128*AP] | stage0{Kh,Kl,Vh,Vl each 64*AP} | stage1{...}
    const int tid = threadIdx.x, wid = tid >> 5, lane = tid & 31;
    const int bh = blockIdx.y, b = bh >> 3, h = bh & 7;
    const int q0 = blockIdx.x * 128;
    const int bN = b * NTOK;
    const uint32_t base = smem_u32(sma);
    const uint32_t offQl = 128 * AP * 2;
    const uint32_t offKV = 2 * 128 * AP * 2;

    // Load Q tile (hi/lo), 128x64
#pragma unroll
    for (int it = 0; it < 4; it++) {
        int i = tid + it * 256;
        int r = i >> 3, u = i & 7;
        size_t go = (size_t)(bN + q0 + r) * DIMM + h * DHD + u * 8;
        *reinterpret_cast<uint4*>(sma + r * AP + u * 8)            = *reinterpret_cast<const uint4*>(qh + go);
        *reinterpret_cast<uint4*>(sma + 128 * AP + r * AP + u * 8) = *reinterpret_cast<const uint4*>(ql + go);
    }

    float o[8][4];
#pragma unroll
    for (int nt = 0; nt < 8; nt++)
#pragma unroll
        for (int j = 0; j < 4; j++) o[nt][j] = 0.0f;
    float mi[2] = {-1e30f, -1e30f};
    float li[2] = {0.f, 0.f};

    const int lr = lane & 15, lc = (lane >> 4) * 8;

    // Prologue: prefetch tile 0 into stage 0
    {
        const uint32_t kb = base + offKV;
#pragma unroll
        for (int it = 0; it < 2; it++) {
            int i = tid + it * 256;
            int r = i >> 3, u = i & 7;
            size_t gk = (size_t)(bN + r) * (2 * DIMM) + h * DHD + u * 8;
            uint32_t d = kb + (uint32_t)((r * AP + u * 8) * 2);
            CP16(d,         kvh + gk);
            CP16(d + 9216,  kvl + gk);
            CP16(d + 18432, kvh + gk + DIMM);
            CP16(d + 27648, kvl + gk + DIMM);
        }
        CP_COMMIT();
    }

    for (int t = 0; t < 33; t++) {
        const int stage = t & 1;
        const uint32_t kb = base + offKV + stage * KVSTAGE_B;

        if (t < 32) CP_WAIT0();
        __syncthreads();

        if (t + 1 < 32) {
            const uint32_t kb2 = base + offKV + (stage ^ 1) * KVSTAGE_B;
#pragma unroll
            for (int it = 0; it < 2; it++) {
                int i = tid + it * 256;
                int r = i >> 3, u = i & 7;
                size_t gk = (size_t)(bN + (t + 1) * 64 + r) * (2 * DIMM) + h * DHD + u * 8;
                uint32_t d = kb2 + (uint32_t)((r * AP + u * 8) * 2);
                CP16(d,         kvh + gk);
                CP16(d + 9216,  kvl + gk);
                CP16(d + 18432, kvh + gk + DIMM);
                CP16(d + 27648, kvl + gk + DIMM);
            }
            CP_COMMIT();
        }

        if (t == 32) {
            __nv_bfloat16* skv = sma + 2 * 128 * AP;  // stage 0
            uint4 z = {0u, 0u, 0u, 0u};
#pragma unroll
            for (int it = 0; it < 9; it++)
                *(reinterpret_cast<uint4*>(skv) + tid + it * 256) = z;
            __syncthreads();
            if (tid < MTOK * 64) {
                int kk = tid >> 6, dd = tid & 63;
                int mi_ = h * (MTOK * DHD) + kk * DHD + dd;
                float kval = SQRT_DH * mk[mi_];
                float vval = SQRT_M  * mv[mi_];
                __nv_bfloat16 khh = __float2bfloat16(kval);
                skv[kk * AP + dd]           = khh;
                skv[64 * AP + kk * AP + dd] = __float2bfloat16(kval - __bfloat162float(khh));
                __nv_bfloat16 vhh = __float2bfloat16(vval);
                skv[2 * 64 * AP + kk * AP + dd] = vhh;
                skv[3 * 64 * AP + kk * AP + dd] = __float2bfloat16(vval - __bfloat162float(vhh));
            }
            __syncthreads();
        }
        const uint32_t kbc = (t == 32) ? (base + offKV) : kb;

        // ---- S = Q K^T (m16 x n64 per warp) ----
        float s[8][4];
#pragma unroll
        for (int nt = 0; nt < 8; nt++)
#pragma unroll
            for (int j = 0; j < 4; j++) s[nt][j] = 0.0f;

#pragma unroll
        for (int kt = 0; kt < 4; kt++) {
            uint32_t ah[4], al[4];
            uint32_t ad = base + (uint32_t)(((wid * 16 + lr) * AP + kt * 16 + lc) * 2);
            ldsm4(ah, ad);
            ldsm4(al, ad + offQl);
#pragma unroll
            for (int np = 0; np < 4; np++) {
                uint32_t r4[4], l4[4];
                uint32_t kd = kbc + (uint32_t)(((np * 16 + lr) * AP + kt * 16 + lc) * 2);
                ldsm4(r4, kd);
                ldsm4(l4, kd + 9216);
                uint32_t bh0[2] = {r4[0], r4[2]}, bh1[2] = {r4[1], r4[3]};
                uint32_t bl0[2] = {l4[0], l4[2]}, bl1[2] = {l4[1], l4[3]};
                mma16816(s[2 * np],     ah, bh0);
                mma16816(s[2 * np],     ah, bl0);
                mma16816(s[2 * np],     al, bh0);
                mma16816(s[2 * np + 1], ah, bh1);
                mma16816(s[2 * np + 1], ah, bl1);
                mma16816(s[2 * np + 1], al, bh1);
            }
        }

        if (t == 32) {
#pragma unroll
            for (int nt = 0; nt < 8; nt++) {
                int c0 = nt * 8 + (lane & 3) * 2;
                if (c0 >= MTOK)     { s[nt][0] = -1e30f; s[nt][2] = -1e30f; }
                if (c0 + 1 >= MTOK) { s[nt][1] = -1e30f; s[nt][3] = -1e30f; }
            }
        }

        // ---- online softmax (exp2 domain) ----
#pragma unroll
        for (int hh = 0; hh < 2; hh++) {
            float rm = -1e30f;
#pragma unroll
            for (int nt = 0; nt < 8; nt++) {
                rm = fmaxf(rm, s[nt][2 * hh]);
                rm = fmaxf(rm, s[nt][2 * hh + 1]);
            }
            rm = fmaxf(rm, __shfl_xor_sync(0xffffffffu, rm, 1));
            rm = fmaxf(rm, __shfl_xor_sync(0xffffffffu, rm, 2));
            float mn = fmaxf(mi[hh], rm);
            float alpha = fast_exp2(mi[hh] - mn);
            float sum = 0.f;
#pragma unroll
            for (int nt = 0; nt < 8; nt++) {
                float p0 = fast_exp2(s[nt][2 * hh]     - mn);
                float p1 = fast_exp2(s[nt][2 * hh + 1] - mn);
                s[nt][2 * hh]     = p0;
                s[nt][2 * hh + 1] = p1;
                sum += p0 + p1;
            }
            sum += __shfl_xor_sync(0xffffffffu, sum, 1);
            sum += __shfl_xor_sync(0xffffffffu, sum, 2);
            li[hh] = li[hh] * alpha + sum;
            mi[hh] = mn;
#pragma unroll
            for (int nt = 0; nt < 8; nt++) {
                o[nt][2 * hh]     *= alpha;
                o[nt][2 * hh + 1] *= alpha;
            }
        }

        // ---- O += P V (V ldsm interleaved; only 8 V regs live) ----
#pragma unroll
        for (int kt = 0; kt < 4; kt++) {
            uint32_t aph[4], apl[4];
            pack_split(s[2 * kt][0],     s[2 * kt][1],     aph[0], apl[0]);
            pack_split(s[2 * kt][2],     s[2 * kt][3],     aph[1], apl[1]);
            pack_split(s[2 * kt + 1][0], s[2 * kt + 1][1], aph[2], apl[2]);
            pack_split(s[2 * kt + 1][2], s[2 * kt + 1][3], aph[3], apl[3]);
#pragma unroll
            for (int np = 0; np < 4; np++) {
                uint32_t r4[4], l4[4];
                uint32_t vd = kbc + 18432 + (uint32_t)(((kt * 16 + lr) * AP + np * 16 + lc) * 2);
                ldsm4t(r4, vd);
                ldsm4t(l4, vd + 9216);
                uint32_t vh0[2] = {r4[0], r4[1]}, vh1[2] = {r4[2], r4[3]};
                uint32_t vl0[2] = {l4[0], l4[1]}, vl1[2] = {l4[2], l4[3]};
                mma16816(o[2 * np],     aph, vh0);
                mma16816(o[2 * np],     aph, vl0);
                mma16816(o[2 * np],     apl, vh0);
                mma16816(o[2 * np + 1], aph, vh1);
                mma16816(o[2 * np + 1], aph, vl1);
                mma16816(o[2 * np + 1], apl, vh1);
            }
        }
    }

    // ---- normalize + write bf16 hi/lo ----
    float inv[2] = {__fdividef(1.0f, li[0]), __fdividef(1.0f, li[1])};

#pragma unroll
    for (int nt = 0; nt < 8; nt++) {
        int r = q0 + wid * 16 + (lane >> 2);
        int c = h * DHD + nt * 8 + (lane & 3) * 2;
        uint32_t ph, pl;
        pack_split(o[nt][0] * inv[0], o[nt][1] * inv[0], ph, pl);
        *reinterpret_cast<uint32_t*>(oh + (size_t)(bN + r) * DIMM + c) = ph;
        *reinterpret_cast<uint32_t*>(ol + (size_t)(bN + r) * DIMM + c) = pl;
        pack_split(o[nt][2] * inv[1], o[nt][3] * inv[1], ph, pl);
        *reinterpret_cast<uint32_t*>(oh + (size_t)(bN + r + 8) * DIMM + c) = ph;
        *reinterpret_cast<uint32_t*>(ol + (size_t)(bN + r + 8) * DIMM + c) = pl;
    }
}

// ---------------------------------------------------------------------------
extern "C" void kernel_launch(void* const* d_in, const int* in_sizes, int n_in,
                              void* d_out, int out_size)
{
    const float* x   = (const float*)d_in[0];
    const float* wq  = (const float*)d_in[1];
    const float* wkv = (const float*)d_in[2];
    const float* wo  = (const float*)d_in[3];
    const float* bo  = (const float*)d_in[4];
    const float* m_k = (const float*)d_in[5];
    const float* m_v = (const float*)d_in[6];
    float* out = (float*)d_out;

    __nv_bfloat16 *xh, *xl, *qh, *ql, *kvh, *kvl, *ohp, *olp;
    __nv_bfloat16 *w3h, *w3l, *woh, *wol;
    cudaGetSymbolAddress((void**)&xh,   g_xh);   cudaGetSymbolAddress((void**)&xl,   g_xl);
    cudaGetSymbolAddress((void**)&qh,   g_qh);   cudaGetSymbolAddress((void**)&ql,   g_ql);
    cudaGetSymbolAddress((void**)&kvh,  g_kvh);  cudaGetSymbolAddress((void**)&kvl,  g_kvl);
    cudaGetSymbolAddress((void**)&ohp,  g_oh);   cudaGetSymbolAddress((void**)&olp,  g_ol);
    cudaGetSymbolAddress((void**)&w3h,  g_w3h);  cudaGetSymbolAddress((void**)&w3l,  g_w3l);
    cudaGetSymbolAddress((void**)&woh,  g_woh);  cudaGetSymbolAddress((void**)&wol,  g_wol);

    const int GEMM_SMEM = 4 * 128 * GP * sizeof(__nv_bfloat16);
    const int ATTN_SMEM = (2 * 128 * AP) * (int)sizeof(__nv_bfloat16) + 2 * KVSTAGE_B;
    cudaFuncSetAttribute(mma_gemm_kernel, cudaFuncAttributeMaxDynamicSharedMemorySize, GEMM_SMEM);
    cudaFuncSetAttribute(mma_attn_kernel, cudaFuncAttributeMaxDynamicSharedMemorySize, ATTN_SMEM);

    // Prep
    split_scale_kernel<<<(MROWS * KDIM / 4 + 255) / 256, 256>>>(x, xh, xl, MROWS * KDIM);
    {
        dim3 grid(32, KDIM / 64);
        transpose_split_all<<<grid, 256>>>(wq, wkv, wo, w3h, w3l, woh, wol);
    }

    // Fused Q+KV projection (N=1536)
    {
        dim3 grid(3 * DIMM / 128, MROWS / 128);
        mma_gemm_kernel<<<grid, 256, GEMM_SMEM>>>(xh, xl, w3h, w3l,
            nullptr, nullptr, qh, ql, kvh, kvl, 0);
    }
    // Attention
    {
        dim3 grid(NTOK / 128, NB * NH);
        mma_attn_kernel<<<grid, 256, ATTN_SMEM>>>(qh, ql, kvh, kvl, m_k, m_v, ohp, olp);
    }
    // Output projection (+bias) -> fp32
    {
        dim3 grid(DIMM / 128, MROWS / 128);
        mma_gemm_kernel<<<grid, 256, GEMM_SMEM>>>(ohp, olp, woh, wol,
            out, bo, nullptr, nullptr, nullptr, nullptr, 1);
    }
}

// round 6
// speedup vs baseline: 4.0276x; 1.2752x over previous
#include <cuda_runtime.h>
#include <cuda_bf16.h>
#include <cuda_fp16.h>
#include <cstdint>

// Problem constants
#define NB    2
#define NTOK  2048
#define DIMM  512
#define NH    8
#define DHD   64
#define MTOK  3
#define SQRT_DH 8.0f
#define SQRT_M  1.7320508075688772f
#define SCALE   0.125f
#define LOG2E   1.4426950408889634f
#define QSCALE  (SCALE * LOG2E)
#define MROWS (NB * NTOK)   // 4096
#define KDIM  512

// ---------------------------------------------------------------------------
// Scratch
// ---------------------------------------------------------------------------
__device__ __nv_bfloat16 g_xh[MROWS * KDIM],     g_xl[MROWS * KDIM];
__device__ __half        g_qh[MROWS * DIMM],     g_ql[MROWS * DIMM];
__device__ __half        g_kh[MROWS * DIMM];
__device__ __half        g_vh[MROWS * DIMM],     g_vl[MROWS * DIMM];
__device__ __nv_bfloat16 g_oh[MROWS * DIMM],     g_ol[MROWS * DIMM];
__device__ __nv_bfloat16 g_w3h[3 * DIMM * KDIM], g_w3l[3 * DIMM * KDIM];
__device__ __nv_bfloat16 g_woh[DIMM * KDIM],     g_wol[DIMM * KDIM];

// ---------------------------------------------------------------------------
// Warp-MMA primitives
// ---------------------------------------------------------------------------
__device__ __forceinline__ uint32_t smem_u32(const void* p) {
    uint32_t a;
    asm("{ .reg .u64 t; cvta.to.shared.u64 t, %1; cvt.u32.u64 %0, t; }" : "=r"(a) : "l"(p));
    return a;
}
__device__ __forceinline__ void ldsm4(uint32_t* r, uint32_t a) {
    asm volatile("ldmatrix.sync.aligned.m8n8.x4.shared.b16 {%0,%1,%2,%3}, [%4];"
                 : "=r"(r[0]), "=r"(r[1]), "=r"(r[2]), "=r"(r[3]) : "r"(a));
}
__device__ __forceinline__ void ldsm4t(uint32_t* r, uint32_t a) {
    asm volatile("ldmatrix.sync.aligned.m8n8.x4.trans.shared.b16 {%0,%1,%2,%3}, [%4];"
                 : "=r"(r[0]), "=r"(r[1]), "=r"(r[2]), "=r"(r[3]) : "r"(a));
}
__device__ __forceinline__ void mma16816(float* c, const uint32_t* a, const uint32_t* b) {
    asm volatile(
        "mma.sync.aligned.m16n8k16.row.col.f32.bf16.bf16.f32 "
        "{%0,%1,%2,%3}, {%4,%5,%6,%7}, {%8,%9}, {%0,%1,%2,%3};"
        : "+f"(c[0]), "+f"(c[1]), "+f"(c[2]), "+f"(c[3])
        : "r"(a[0]), "r"(a[1]), "r"(a[2]), "r"(a[3]), "r"(b[0]), "r"(b[1]));
}
__device__ __forceinline__ void mma16816h(float* c, const uint32_t* a, const uint32_t* b) {
    asm volatile(
        "mma.sync.aligned.m16n8k16.row.col.f32.f16.f16.f32 "
        "{%0,%1,%2,%3}, {%4,%5,%6,%7}, {%8,%9}, {%0,%1,%2,%3};"
        : "+f"(c[0]), "+f"(c[1]), "+f"(c[2]), "+f"(c[3])
        : "r"(a[0]), "r"(a[1]), "r"(a[2]), "r"(a[3]), "r"(b[0]), "r"(b[1]));
}
#define CP16(dst, src) \
    asm volatile("cp.async.cg.shared.global [%0], [%1], 16;" :: "r"(dst), "l"(src))
#define CP_COMMIT() asm volatile("cp.async.commit_group;" ::: "memory")
#define CP_WAIT0()  asm volatile("cp.async.wait_group 0;" ::: "memory")

__device__ __forceinline__ float fast_exp2(float x) {
    float r;
    asm("ex2.approx.f32 %0, %1;" : "=f"(r) : "f"(x));
    return r;
}
__device__ __forceinline__ void pack_split(float x, float y, uint32_t& h, uint32_t& l) {
    __nv_bfloat162 hh = __floats2bfloat162_rn(x, y);
    float2 hf = __bfloat1622float2(hh);
    __nv_bfloat162 ll = __floats2bfloat162_rn(x - hf.x, y - hf.y);
    h = reinterpret_cast<uint32_t&>(hh);
    l = reinterpret_cast<uint32_t&>(ll);
}
__device__ __forceinline__ void pack_split_h(float x, float y, uint32_t& h, uint32_t& l) {
    __half2 hh = __floats2half2_rn(x, y);
    float2 hf = __half22float2(hh);
    __half2 ll = __floats2half2_rn(x - hf.x, y - hf.y);
    h = reinterpret_cast<uint32_t&>(hh);
    l = reinterpret_cast<uint32_t&>(ll);
}
__device__ __forceinline__ uint32_t h2pack(float x, float y) {
    __half2 v = __floats2half2_rn(x, y);
    return reinterpret_cast<uint32_t&>(v);
}

// ---------------------------------------------------------------------------
// Prep kernels
// ---------------------------------------------------------------------------
__global__ void __launch_bounds__(256) split_scale_kernel(
    const float* __restrict__ in, __nv_bfloat16* __restrict__ hi,
    __nv_bfloat16* __restrict__ lo, int n)
{
    int i = (blockIdx.x * 256 + threadIdx.x) * 4;
    if (i >= n) return;
    float4 v = *reinterpret_cast<const float4*>(in + i);
    uint32_t h0, l0, h1, l1;
    pack_split(v.x, v.y, h0, l0);
    pack_split(v.z, v.w, h1, l1);
    *reinterpret_cast<uint32_t*>(hi + i)     = h0;
    *reinterpret_cast<uint32_t*>(hi + i + 2) = h1;
    *reinterpret_cast<uint32_t*>(lo + i)     = l0;
    *reinterpret_cast<uint32_t*>(lo + i + 2) = l1;
}

__global__ void __launch_bounds__(256) transpose_split_all(
    const float* __restrict__ wq, const float* __restrict__ wkv,
    const float* __restrict__ wo,
    __nv_bfloat16* __restrict__ w3h, __nv_bfloat16* __restrict__ w3l,
    __nv_bfloat16* __restrict__ woh, __nv_bfloat16* __restrict__ wol)
{
    __shared__ float tile[64][65];
    const int tid = threadIdx.x;
    const int ct = blockIdx.x;
    const int k0 = blockIdx.y * 64;

    const float* src;
    __nv_bfloat16 *dh, *dl;
    int N, n0, rowOff;
    if (ct < 8)       { src = wq;  N = 512;  n0 = ct * 64;        dh = w3h; dl = w3l; rowOff = 0; }
    else if (ct < 24) { src = wkv; N = 1024; n0 = (ct - 8) * 64;  dh = w3h; dl = w3l; rowOff = DIMM; }
    else              { src = wo;  N = 512;  n0 = (ct - 24) * 64; dh = woh; dl = wol; rowOff = 0; }

#pragma unroll
    for (int it = 0; it < 4; it++) {
        int idx = tid + it * 256;
        int r = idx >> 4, c4 = (idx & 15) * 4;
        float4 v = *reinterpret_cast<const float4*>(src + (size_t)(k0 + r) * N + n0 + c4);
        tile[r][c4 + 0] = v.x; tile[r][c4 + 1] = v.y;
        tile[r][c4 + 2] = v.z; tile[r][c4 + 3] = v.w;
    }
    __syncthreads();
#pragma unroll
    for (int it = 0; it < 4; it++) {
        int idx = tid + it * 256;
        int n = idx >> 4, kg = idx & 15;
        float v0 = tile[kg * 4 + 0][n], v1 = tile[kg * 4 + 1][n];
        float v2 = tile[kg * 4 + 2][n], v3 = tile[kg * 4 + 3][n];
        uint32_t h0, l0, h1, l1;
        pack_split(v0, v1, h0, l0);
        pack_split(v2, v3, h1, l1);
        size_t dst = (size_t)(rowOff + n0 + n) * KDIM + k0 + kg * 4;
        *reinterpret_cast<uint2*>(dh + dst) = make_uint2(h0, h1);
        *reinterpret_cast<uint2*>(dl + dst) = make_uint2(l0, l1);
    }
}

// ---------------------------------------------------------------------------
// HMMA GEMM, 2-stage cp.async pipeline. CTA 128x128, 8 warps, BK=32 x 16 chunks.
// mode 0: fused QKV epilogue (Q fp16 hi/lo QSCALE'd; K fp16; V fp16 hi/lo)
// mode 1: fp32 + bias
// ---------------------------------------------------------------------------
#define GPAD 40
#define GST_B (4 * 128 * GPAD * 2)   // 40960 bytes per stage

__global__ void __launch_bounds__(256, 2) mma_gemm_kernel(
    const __nv_bfloat16* __restrict__ Ah, const __nv_bfloat16* __restrict__ Al,
    const __nv_bfloat16* __restrict__ BTh, const __nv_bfloat16* __restrict__ BTl,
    float* __restrict__ Cf, const float* __restrict__ bias,
    __half* __restrict__ Qh, __half* __restrict__ Ql, __half* __restrict__ Kh,
    __half* __restrict__ Vh, __half* __restrict__ Vl, int mode)
{
    extern __shared__ __nv_bfloat16 sg[];
    const int tid = threadIdx.x, wid = tid >> 5, lane = tid & 31;
    const int row0 = blockIdx.y * 128, col0 = blockIdx.x * 128;
    const int wm = (wid & 3) * 32, wn = (wid >> 2) * 64;
    const uint32_t base = smem_u32(sg);
    const int lr = lane & 15, lc = (lane >> 4) * 8;

    float acc[2][8][4];
#pragma unroll
    for (int mt = 0; mt < 2; mt++)
#pragma unroll
        for (int nt = 0; nt < 8; nt++)
#pragma unroll
            for (int j = 0; j < 4; j++) acc[mt][nt][j] = 0.0f;

    auto prefetch = [&](int c, int st) {
        int k0 = c * 32;
        uint32_t sb = base + st * GST_B;
#pragma unroll
        for (int it = 0; it < 2; it++) {
            int i = tid + it * 256;        // 0..511
            int r = i >> 2, u = i & 3;     // 128 rows x 4 16B-units
            size_t ga = (size_t)(row0 + r) * KDIM + k0 + u * 8;
            size_t gb = (size_t)(col0 + r) * KDIM + k0 + u * 8;
            uint32_t d = sb + (uint32_t)((r * GPAD + u * 8) * 2);
            CP16(d,         Ah + ga);
            CP16(d + 10240, Al + ga);
            CP16(d + 20480, BTh + gb);
            CP16(d + 30720, BTl + gb);
        }
    };

    prefetch(0, 0);
    CP_COMMIT();

    for (int c = 0; c < 16; c++) {
        CP_WAIT0();
        __syncthreads();
        if (c + 1 < 16) { prefetch(c + 1, (c + 1) & 1); CP_COMMIT(); }

        uint32_t sb = base + (c & 1) * GST_B;
#pragma unroll
        for (int kt = 0; kt < 2; kt++) {
            uint32_t ah[2][4], al[2][4];
#pragma unroll
            for (int mt = 0; mt < 2; mt++) {
                uint32_t ad = sb + (uint32_t)(((wm + mt * 16 + lr) * GPAD + kt * 16 + lc) * 2);
                ldsm4(ah[mt], ad);
                ldsm4(al[mt], ad + 10240);
            }
#pragma unroll
            for (int np = 0; np < 4; np++) {
                uint32_t r4[4], l4[4];
                uint32_t bd = sb + 20480 + (uint32_t)(((wn + np * 16 + lr) * GPAD + kt * 16 + lc) * 2);
                ldsm4(r4, bd);
                ldsm4(l4, bd + 10240);
                uint32_t bh0[2] = {r4[0], r4[2]}, bh1[2] = {r4[1], r4[3]};
                uint32_t bl0[2] = {l4[0], l4[2]}, bl1[2] = {l4[1], l4[3]};
#pragma unroll
                for (int mt = 0; mt < 2; mt++) {
                    mma16816(acc[mt][2 * np],     ah[mt], bh0);
                    mma16816(acc[mt][2 * np],     ah[mt], bl0);
                    mma16816(acc[mt][2 * np],     al[mt], bh0);
                    mma16816(acc[mt][2 * np + 1], ah[mt], bh1);
                    mma16816(acc[mt][2 * np + 1], ah[mt], bl1);
                    mma16816(acc[mt][2 * np + 1], al[mt], bh1);
                }
            }
        }
    }

    if (mode == 1) {
#pragma unroll
        for (int mt = 0; mt < 2; mt++) {
#pragma unroll
            for (int nt = 0; nt < 8; nt++) {
                int r = row0 + wm + mt * 16 + (lane >> 2);
                int c = col0 + wn + nt * 8 + (lane & 3) * 2;
                float b0 = bias[c], b1 = bias[c + 1];
                float2 v0 = {acc[mt][nt][0] + b0, acc[mt][nt][1] + b1};
                float2 v1 = {acc[mt][nt][2] + b0, acc[mt][nt][3] + b1};
                *reinterpret_cast<float2*>(Cf + (size_t)r * DIMM + c)       = v0;
                *reinterpret_cast<float2*>(Cf + (size_t)(r + 8) * DIMM + c) = v1;
            }
        }
    } else if (col0 < 512) {           // Q: fp16 hi/lo, QSCALE
#pragma unroll
        for (int mt = 0; mt < 2; mt++) {
#pragma unroll
            for (int nt = 0; nt < 8; nt++) {
                int r = row0 + wm + mt * 16 + (lane >> 2);
                int c = col0 + wn + nt * 8 + (lane & 3) * 2;
                uint32_t h, l;
                pack_split_h(acc[mt][nt][0] * QSCALE, acc[mt][nt][1] * QSCALE, h, l);
                *reinterpret_cast<uint32_t*>(Qh + (size_t)r * DIMM + c) = h;
                *reinterpret_cast<uint32_t*>(Ql + (size_t)r * DIMM + c) = l;
                pack_split_h(acc[mt][nt][2] * QSCALE, acc[mt][nt][3] * QSCALE, h, l);
                *reinterpret_cast<uint32_t*>(Qh + (size_t)(r + 8) * DIMM + c) = h;
                *reinterpret_cast<uint32_t*>(Ql + (size_t)(r + 8) * DIMM + c) = l;
            }
        }
    } else if (col0 < 1024) {          // K: single fp16
#pragma unroll
        for (int mt = 0; mt < 2; mt++) {
#pragma unroll
            for (int nt = 0; nt < 8; nt++) {
                int r = row0 + wm + mt * 16 + (lane >> 2);
                int c = col0 - 512 + wn + nt * 8 + (lane & 3) * 2;
                *reinterpret_cast<uint32_t*>(Kh + (size_t)r * DIMM + c) =
                    h2pack(acc[mt][nt][0], acc[mt][nt][1]);
                *reinterpret_cast<uint32_t*>(Kh + (size_t)(r + 8) * DIMM + c) =
                    h2pack(acc[mt][nt][2], acc[mt][nt][3]);
            }
        }
    } else {                           // V: fp16 hi/lo
#pragma unroll
        for (int mt = 0; mt < 2; mt++) {
#pragma unroll
            for (int nt = 0; nt < 8; nt++) {
                int r = row0 + wm + mt * 16 + (lane >> 2);
                int c = col0 - 1024 + wn + nt * 8 + (lane & 3) * 2;
                uint32_t h, l;
                pack_split_h(acc[mt][nt][0], acc[mt][nt][1], h, l);
                *reinterpret_cast<uint32_t*>(Vh + (size_t)r * DIMM + c) = h;
                *reinterpret_cast<uint32_t*>(Vl + (size_t)r * DIMM + c) = l;
                pack_split_h(acc[mt][nt][2], acc[mt][nt][3], h, l);
                *reinterpret_cast<uint32_t*>(Vh + (size_t)(r + 8) * DIMM + c) = h;
                *reinterpret_cast<uint32_t*>(Vl + (size_t)(r + 8) * DIMM + c) = l;
            }
        }
    }
}

// ---------------------------------------------------------------------------
// fp16 HMMA flash attention: S = (Qh+Ql) Kh (2 terms), PV = P (Vh+Vl) (2 terms)
// 8 warps (m16 each), cp.async double-buffered K/V, exp2-domain softmax.
// ---------------------------------------------------------------------------
#define AP 72
#define KVST_B (3 * 64 * AP * 2)   // 27648 bytes per stage: K | Vh | Vl

__global__ void __launch_bounds__(256, 2) mma_attn_kernel(
    const __half* __restrict__ qh, const __half* __restrict__ ql,
    const __half* __restrict__ kh,
    const __half* __restrict__ vh, const __half* __restrict__ vl,
    const float* __restrict__ mk, const float* __restrict__ mv,
    __nv_bfloat16* __restrict__ oh, __nv_bfloat16* __restrict__ ol)
{
    extern __shared__ __half smh[];
    // layout: Qh[128*AP] | Ql[128*AP] | stage0{K,Vh,Vl each 64*AP} | stage1{...}
    const int tid = threadIdx.x, wid = tid >> 5, lane = tid & 31;
    const int bh = blockIdx.y, b = bh >> 3, h = bh & 7;
    const int q0 = blockIdx.x * 128;
    const int bN = b * NTOK;
    const uint32_t base = smem_u32(smh);
    const uint32_t offQl = 128 * AP * 2;
    const uint32_t offKV = 2 * 128 * AP * 2;   // 36864

    // Load Q tile (fp16 hi/lo), 128x64
#pragma unroll
    for (int it = 0; it < 4; it++) {
        int i = tid + it * 256;
        int r = i >> 3, u = i & 7;
        size_t go = (size_t)(bN + q0 + r) * DIMM + h * DHD + u * 8;
        *reinterpret_cast<uint4*>(smh + r * AP + u * 8)            = *reinterpret_cast<const uint4*>(qh + go);
        *reinterpret_cast<uint4*>(smh + 128 * AP + r * AP + u * 8) = *reinterpret_cast<const uint4*>(ql + go);
    }

    float o[8][4];
#pragma unroll
    for (int nt = 0; nt < 8; nt++)
#pragma unroll
        for (int j = 0; j < 4; j++) o[nt][j] = 0.0f;
    float mi[2] = {-1e30f, -1e30f};
    float li[2] = {0.f, 0.f};

    const int lr = lane & 15, lc = (lane >> 4) * 8;

    // Prologue: prefetch tile 0 into stage 0
    {
        const uint32_t kb = base + offKV;
#pragma unroll
        for (int it = 0; it < 2; it++) {
            int i = tid + it * 256;
            int r = i >> 3, u = i & 7;
            size_t gk = (size_t)(bN + r) * DIMM + h * DHD + u * 8;
            uint32_t d = kb + (uint32_t)((r * AP + u * 8) * 2);
            CP16(d,         kh + gk);
            CP16(d + 9216,  vh + gk);
            CP16(d + 18432, vl + gk);
        }
        CP_COMMIT();
    }

    for (int t = 0; t < 33; t++) {
        const int stage = t & 1;

        if (t < 32) CP_WAIT0();
        __syncthreads();

        if (t + 1 < 32) {
            const uint32_t kb2 = base + offKV + (stage ^ 1) * KVST_B;
#pragma unroll
            for (int it = 0; it < 2; it++) {
                int i = tid + it * 256;
                int r = i >> 3, u = i & 7;
                size_t gk = (size_t)(bN + (t + 1) * 64 + r) * DIMM + h * DHD + u * 8;
                uint32_t d = kb2 + (uint32_t)((r * AP + u * 8) * 2);
                CP16(d,         kh + gk);
                CP16(d + 9216,  vh + gk);
                CP16(d + 18432, vl + gk);
            }
            CP_COMMIT();
        }

        if (t == 32) {
            __half* skv = smh + 2 * 128 * AP;  // stage 0
            uint4 z = {0u, 0u, 0u, 0u};
#pragma unroll
            for (int it = 0; it < 7; it++) {
                int idx = tid + it * 256;
                if (idx < 1728) *(reinterpret_cast<uint4*>(skv) + idx) = z;
            }
            __syncthreads();
            if (tid < MTOK * 64) {
                int kk = tid >> 6, dd = tid & 63;
                int mi_ = h * (MTOK * DHD) + kk * DHD + dd;
                skv[kk * AP + dd] = __float2half(SQRT_DH * mk[mi_]);
                float vval = SQRT_M * mv[mi_];
                __half vhh = __float2half(vval);
                skv[64 * AP + kk * AP + dd]     = vhh;
                skv[2 * 64 * AP + kk * AP + dd] = __float2half(vval - __half2float(vhh));
            }
            __syncthreads();
        }
        const uint32_t kbc = base + offKV + ((t == 32) ? 0 : stage * KVST_B);

        // ---- S = (Qh+Ql) K^T ----
        float s[8][4];
#pragma unroll
        for (int nt = 0; nt < 8; nt++)
#pragma unroll
            for (int j = 0; j < 4; j++) s[nt][j] = 0.0f;

#pragma unroll
        for (int kt = 0; kt < 4; kt++) {
            uint32_t aqh[4], aql[4];
            uint32_t ad = base + (uint32_t)(((wid * 16 + lr) * AP + kt * 16 + lc) * 2);
            ldsm4(aqh, ad);
            ldsm4(aql, ad + offQl);
#pragma unroll
            for (int np = 0; np < 4; np++) {
                uint32_t r4[4];
                uint32_t kd = kbc + (uint32_t)(((np * 16 + lr) * AP + kt * 16 + lc) * 2);
                ldsm4(r4, kd);
                uint32_t bh0[2] = {r4[0], r4[2]}, bh1[2] = {r4[1], r4[3]};
                mma16816h(s[2 * np],     aqh, bh0);
                mma16816h(s[2 * np],     aql, bh0);
                mma16816h(s[2 * np + 1], aqh, bh1);
                mma16816h(s[2 * np + 1], aql, bh1);
            }
        }

        if (t == 32) {
#pragma unroll
            for (int nt = 0; nt < 8; nt++) {
                int c0 = nt * 8 + (lane & 3) * 2;
                if (c0 >= MTOK)     { s[nt][0] = -1e30f; s[nt][2] = -1e30f; }
                if (c0 + 1 >= MTOK) { s[nt][1] = -1e30f; s[nt][3] = -1e30f; }
            }
        }

        // ---- online softmax (exp2 domain) ----
#pragma unroll
        for (int hh = 0; hh < 2; hh++) {
            float rm = -1e30f;
#pragma unroll
            for (int nt = 0; nt < 8; nt++) {
                rm = fmaxf(rm, s[nt][2 * hh]);
                rm = fmaxf(rm, s[nt][2 * hh + 1]);
            }
            rm = fmaxf(rm, __shfl_xor_sync(0xffffffffu, rm, 1));
            rm = fmaxf(rm, __shfl_xor_sync(0xffffffffu, rm, 2));
            float mn = fmaxf(mi[hh], rm);
            float alpha = fast_exp2(mi[hh] - mn);
            float sum = 0.f;
#pragma unroll
            for (int nt = 0; nt < 8; nt++) {
                float p0 = fast_exp2(s[nt][2 * hh]     - mn);
                float p1 = fast_exp2(s[nt][2 * hh + 1] - mn);
                s[nt][2 * hh]     = p0;
                s[nt][2 * hh + 1] = p1;
                sum += p0 + p1;
            }
            sum += __shfl_xor_sync(0xffffffffu, sum, 1);
            sum += __shfl_xor_sync(0xffffffffu, sum, 2);
            li[hh] = li[hh] * alpha + sum;
            mi[hh] = mn;
#pragma unroll
            for (int nt = 0; nt < 8; nt++) {
                o[nt][2 * hh]     *= alpha;
                o[nt][2 * hh + 1] *= alpha;
            }
        }

        // ---- O += P (Vh+Vl), P single fp16 ----
#pragma unroll
        for (int kt = 0; kt < 4; kt++) {
            uint32_t ap_[4];
            ap_[0] = h2pack(s[2 * kt][0],     s[2 * kt][1]);
            ap_[1] = h2pack(s[2 * kt][2],     s[2 * kt][3]);
            ap_[2] = h2pack(s[2 * kt + 1][0], s[2 * kt + 1][1]);
            ap_[3] = h2pack(s[2 * kt + 1][2], s[2 * kt + 1][3]);
#pragma unroll
            for (int np = 0; np < 4; np++) {
                uint32_t r4[4], l4[4];
                uint32_t vd = kbc + 9216 + (uint32_t)(((kt * 16 + lr) * AP + np * 16 + lc) * 2);
                ldsm4t(r4, vd);
                ldsm4t(l4, vd + 9216);
                uint32_t vh0[2] = {r4[0], r4[1]}, vh1[2] = {r4[2], r4[3]};
                uint32_t vl0[2] = {l4[0], l4[1]}, vl1[2] = {l4[2], l4[3]};
                mma16816h(o[2 * np],     ap_, vh0);
                mma16816h(o[2 * np],     ap_, vl0);
                mma16816h(o[2 * np + 1], ap_, vh1);
                mma16816h(o[2 * np + 1], ap_, vl1);
            }
        }
    }

    // ---- normalize + write bf16 hi/lo (feeds out-proj) ----
    float inv[2] = {__fdividef(1.0f, li[0]), __fdividef(1.0f, li[1])};

#pragma unroll
    for (int nt = 0; nt < 8; nt++) {
        int r = q0 + wid * 16 + (lane >> 2);
        int c = h * DHD + nt * 8 + (lane & 3) * 2;
        uint32_t ph, pl;
        pack_split(o[nt][0] * inv[0], o[nt][1] * inv[0], ph, pl);
        *reinterpret_cast<uint32_t*>(oh + (size_t)(bN + r) * DIMM + c) = ph;
        *reinterpret_cast<uint32_t*>(ol + (size_t)(bN + r) * DIMM + c) = pl;
        pack_split(o[nt][2] * inv[1], o[nt][3] * inv[1], ph, pl);
        *reinterpret_cast<uint32_t*>(oh + (size_t)(bN + r + 8) * DIMM + c) = ph;
        *reinterpret_cast<uint32_t*>(ol + (size_t)(bN + r + 8) * DIMM + c) = pl;
    }
}

// ---------------------------------------------------------------------------
extern "C" void kernel_launch(void* const* d_in, const int* in_sizes, int n_in,
                              void* d_out, int out_size)
{
    const float* x   = (const float*)d_in[0];
    const float* wq  = (const float*)d_in[1];
    const float* wkv = (const float*)d_in[2];
    const float* wo  = (const float*)d_in[3];
    const float* bo  = (const float*)d_in[4];
    const float* m_k = (const float*)d_in[5];
    const float* m_v = (const float*)d_in[6];
    float* out = (float*)d_out;

    __nv_bfloat16 *xh, *xl, *ohp, *olp, *w3h, *w3l, *woh, *wol;
    __half *pqh, *pql, *pkh, *pvh, *pvl;
    cudaGetSymbolAddress((void**)&xh,  g_xh);  cudaGetSymbolAddress((void**)&xl,  g_xl);
    cudaGetSymbolAddress((void**)&pqh, g_qh);  cudaGetSymbolAddress((void**)&pql, g_ql);
    cudaGetSymbolAddress((void**)&pkh, g_kh);
    cudaGetSymbolAddress((void**)&pvh, g_vh);  cudaGetSymbolAddress((void**)&pvl, g_vl);
    cudaGetSymbolAddress((void**)&ohp, g_oh);  cudaGetSymbolAddress((void**)&olp, g_ol);
    cudaGetSymbolAddress((void**)&w3h, g_w3h); cudaGetSymbolAddress((void**)&w3l, g_w3l);
    cudaGetSymbolAddress((void**)&woh, g_woh); cudaGetSymbolAddress((void**)&wol, g_wol);

    const int GEMM_SMEM = 2 * GST_B;                       // 81920
    const int ATTN_SMEM = 2 * 128 * AP * 2 + 2 * KVST_B;   // 92160
    cudaFuncSetAttribute(mma_gemm_kernel, cudaFuncAttributeMaxDynamicSharedMemorySize, GEMM_SMEM);
    cudaFuncSetAttribute(mma_attn_kernel, cudaFuncAttributeMaxDynamicSharedMemorySize, ATTN_SMEM);

    // Prep
    split_scale_kernel<<<(MROWS * KDIM / 4 + 255) / 256, 256>>>(x, xh, xl, MROWS * KDIM);
    {
        dim3 grid(32, KDIM / 64);
        transpose_split_all<<<grid, 256>>>(wq, wkv, wo, w3h, w3l, woh, wol);
    }

    // Fused Q+KV projection (N=1536)
    {
        dim3 grid(3 * DIMM / 128, MROWS / 128);
        mma_gemm_kernel<<<grid, 256, GEMM_SMEM>>>(xh, xl, w3h, w3l,
            nullptr, nullptr, pqh, pql, pkh, pvh, pvl, 0);
    }
    // Attention
    {
        dim3 grid(NTOK / 128, NB * NH);
        mma_attn_kernel<<<grid, 256, ATTN_SMEM>>>(pqh, pql, pkh, pvh, pvl,
            m_k, m_v, ohp, olp);
    }
    // Output projection (+bias) -> fp32
    {
        dim3 grid(DIMM / 128, MROWS / 128);
        mma_gemm_kernel<<<grid, 256, GEMM_SMEM>>>(ohp, olp, woh, wol,
            out, bo, nullptr, nullptr, nullptr, nullptr, nullptr, 1);
    }
}

// round 7
// speedup vs baseline: 5.8621x; 1.4555x over previous
#include <cuda_runtime.h>
#include <cuda_fp16.h>
#include <cstdint>

// Problem constants
#define NB    2
#define NTOK  2048
#define DIMM  512
#define NH    8
#define DHD   64
#define MTOK  3
#define SQRT_DH 8.0f
#define SQRT_M  1.7320508075688772f
#define SCALE   0.125f
#define LOG2E   1.4426950408889634f
#define QSCALE  (SCALE * LOG2E)
#define MROWS (NB * NTOK)   // 4096
#define KDIM  512

// ---------------------------------------------------------------------------
// Scratch
// ---------------------------------------------------------------------------
__device__ __half g_x[MROWS * KDIM];
__device__ __half g_q[MROWS * DIMM];
__device__ __half g_k[MROWS * DIMM];
__device__ __half g_v[MROWS * DIMM];
__device__ __half g_o[MROWS * DIMM];
__device__ __half g_w3h[3 * DIMM * KDIM], g_w3l[3 * DIMM * KDIM]; // [wq|wk|wv]^T fp16 hi/lo
__device__ __half g_woh[DIMM * KDIM],     g_wol[DIMM * KDIM];

// ---------------------------------------------------------------------------
// Warp-MMA primitives
// ---------------------------------------------------------------------------
__device__ __forceinline__ uint32_t smem_u32(const void* p) {
    uint32_t a;
    asm("{ .reg .u64 t; cvta.to.shared.u64 t, %1; cvt.u32.u64 %0, t; }" : "=r"(a) : "l"(p));
    return a;
}
__device__ __forceinline__ void ldsm4(uint32_t* r, uint32_t a) {
    asm volatile("ldmatrix.sync.aligned.m8n8.x4.shared.b16 {%0,%1,%2,%3}, [%4];"
                 : "=r"(r[0]), "=r"(r[1]), "=r"(r[2]), "=r"(r[3]) : "r"(a));
}
__device__ __forceinline__ void ldsm4t(uint32_t* r, uint32_t a) {
    asm volatile("ldmatrix.sync.aligned.m8n8.x4.trans.shared.b16 {%0,%1,%2,%3}, [%4];"
                 : "=r"(r[0]), "=r"(r[1]), "=r"(r[2]), "=r"(r[3]) : "r"(a));
}
__device__ __forceinline__ void mma16816h(float* c, const uint32_t* a, const uint32_t* b) {
    asm volatile(
        "mma.sync.aligned.m16n8k16.row.col.f32.f16.f16.f32 "
        "{%0,%1,%2,%3}, {%4,%5,%6,%7}, {%8,%9}, {%0,%1,%2,%3};"
        : "+f"(c[0]), "+f"(c[1]), "+f"(c[2]), "+f"(c[3])
        : "r"(a[0]), "r"(a[1]), "r"(a[2]), "r"(a[3]), "r"(b[0]), "r"(b[1]));
}
#define CP16(dst, src) \
    asm volatile("cp.async.cg.shared.global [%0], [%1], 16;" :: "r"(dst), "l"(src))
#define CP_COMMIT() asm volatile("cp.async.commit_group;" ::: "memory")
#define CP_WAIT0()  asm volatile("cp.async.wait_group 0;" ::: "memory")

__device__ __forceinline__ float fast_exp2(float x) {
    float r;
    asm("ex2.approx.f32 %0, %1;" : "=f"(r) : "f"(x));
    return r;
}
__device__ __forceinline__ uint32_t h2pack(float x, float y) {
    __half2 v = __floats2half2_rn(x, y);
    return reinterpret_cast<uint32_t&>(v);
}
__device__ __forceinline__ void pack_split_h(float x, float y, uint32_t& h, uint32_t& l) {
    __half2 hh = __floats2half2_rn(x, y);
    float2 hf = __half22float2(hh);
    __half2 ll = __floats2half2_rn(x - hf.x, y - hf.y);
    h = reinterpret_cast<uint32_t&>(hh);
    l = reinterpret_cast<uint32_t&>(ll);
}

// ---------------------------------------------------------------------------
// Prep kernels
// ---------------------------------------------------------------------------
__global__ void __launch_bounds__(256) convert_x_kernel(
    const float* __restrict__ in, __half* __restrict__ outh, int n)
{
    int i = (blockIdx.x * 256 + threadIdx.x) * 4;
    if (i >= n) return;
    float4 v = *reinterpret_cast<const float4*>(in + i);
    uint2 o;
    o.x = h2pack(v.x, v.y);
    o.y = h2pack(v.z, v.w);
    *reinterpret_cast<uint2*>(outh + i) = o;
}

// Transpose+split to fp16 hi/lo: wq (N=512), wkv (N=1024), wo (N=512)
__global__ void __launch_bounds__(256) transpose_split_all(
    const float* __restrict__ wq, const float* __restrict__ wkv,
    const float* __restrict__ wo,
    __half* __restrict__ w3h, __half* __restrict__ w3l,
    __half* __restrict__ woh, __half* __restrict__ wol)
{
    __shared__ float tile[64][65];
    const int tid = threadIdx.x;
    const int ct = blockIdx.x;       // 0..31
    const int k0 = blockIdx.y * 64;

    const float* src;
    __half *dh, *dl;
    int N, n0, rowOff;
    if (ct < 8)       { src = wq;  N = 512;  n0 = ct * 64;        dh = w3h; dl = w3l; rowOff = 0; }
    else if (ct < 24) { src = wkv; N = 1024; n0 = (ct - 8) * 64;  dh = w3h; dl = w3l; rowOff = DIMM; }
    else              { src = wo;  N = 512;  n0 = (ct - 24) * 64; dh = woh; dl = wol; rowOff = 0; }

#pragma unroll
    for (int it = 0; it < 4; it++) {
        int idx = tid + it * 256;
        int r = idx >> 4, c4 = (idx & 15) * 4;
        float4 v = *reinterpret_cast<const float4*>(src + (size_t)(k0 + r) * N + n0 + c4);
        tile[r][c4 + 0] = v.x; tile[r][c4 + 1] = v.y;
        tile[r][c4 + 2] = v.z; tile[r][c4 + 3] = v.w;
    }
    __syncthreads();
#pragma unroll
    for (int it = 0; it < 4; it++) {
        int idx = tid + it * 256;
        int n = idx >> 4, kg = idx & 15;
        float v0 = tile[kg * 4 + 0][n], v1 = tile[kg * 4 + 1][n];
        float v2 = tile[kg * 4 + 2][n], v3 = tile[kg * 4 + 3][n];
        uint32_t h0, l0, h1, l1;
        pack_split_h(v0, v1, h0, l0);
        pack_split_h(v2, v3, h1, l1);
        size_t dst = (size_t)(rowOff + n0 + n) * KDIM + k0 + kg * 4;
        *reinterpret_cast<uint2*>(dh + dst) = make_uint2(h0, h1);
        *reinterpret_cast<uint2*>(dl + dst) = make_uint2(l0, l1);
    }
}

// ---------------------------------------------------------------------------
// fp16 HMMA GEMM: C = A (fp16) @ (Bh+Bl) (fp16 hi/lo W), 2 terms.
// CTA 128x128, 8 warps, BK=32 x 16 chunks, 2-stage cp.async pipeline.
// mode 0: fused QKV epilogue (Q*QSCALE / K / V, all single fp16)
// mode 1: fp32 + bias
// ---------------------------------------------------------------------------
#define GPAD 40
#define GST_B (3 * 128 * GPAD * 2)   // 30720 bytes per stage: A | Bh | Bl

__global__ void __launch_bounds__(256, 2) mma_gemm_kernel(
    const __half* __restrict__ A,
    const __half* __restrict__ BTh, const __half* __restrict__ BTl,
    float* __restrict__ Cf, const float* __restrict__ bias,
    __half* __restrict__ Qd, __half* __restrict__ Kd, __half* __restrict__ Vd,
    int mode)
{
    extern __shared__ __half sg[];
    const int tid = threadIdx.x, wid = tid >> 5, lane = tid & 31;
    const int row0 = blockIdx.y * 128, col0 = blockIdx.x * 128;
    const int wm = (wid & 3) * 32, wn = (wid >> 2) * 64;
    const uint32_t base = smem_u32(sg);
    const int lr = lane & 15, lc = (lane >> 4) * 8;

    float acc[2][8][4];
#pragma unroll
    for (int mt = 0; mt < 2; mt++)
#pragma unroll
        for (int nt = 0; nt < 8; nt++)
#pragma unroll
            for (int j = 0; j < 4; j++) acc[mt][nt][j] = 0.0f;

    auto prefetch = [&](int c, int st) {
        int k0 = c * 32;
        uint32_t sb = base + st * GST_B;
#pragma unroll
        for (int it = 0; it < 2; it++) {
            int i = tid + it * 256;        // 0..511
            int r = i >> 2, u = i & 3;     // 128 rows x 4 16B-units
            size_t ga = (size_t)(row0 + r) * KDIM + k0 + u * 8;
            size_t gb = (size_t)(col0 + r) * KDIM + k0 + u * 8;
            uint32_t d = sb + (uint32_t)((r * GPAD + u * 8) * 2);
            CP16(d,         A + ga);
            CP16(d + 10240, BTh + gb);
            CP16(d + 20480, BTl + gb);
        }
    };

    prefetch(0, 0);
    CP_COMMIT();

    for (int c = 0; c < 16; c++) {
        CP_WAIT0();
        __syncthreads();
        if (c + 1 < 16) { prefetch(c + 1, (c + 1) & 1); CP_COMMIT(); }

        uint32_t sb = base + (c & 1) * GST_B;
#pragma unroll
        for (int kt = 0; kt < 2; kt++) {
            uint32_t ah[2][4];
#pragma unroll
            for (int mt = 0; mt < 2; mt++)
                ldsm4(ah[mt], sb + (uint32_t)(((wm + mt * 16 + lr) * GPAD + kt * 16 + lc) * 2));
#pragma unroll
            for (int np = 0; np < 4; np++) {
                uint32_t r4[4], l4[4];
                uint32_t bd = sb + 10240 + (uint32_t)(((wn + np * 16 + lr) * GPAD + kt * 16 + lc) * 2);
                ldsm4(r4, bd);
                ldsm4(l4, bd + 10240);
                uint32_t bh0[2] = {r4[0], r4[2]}, bh1[2] = {r4[1], r4[3]};
                uint32_t bl0[2] = {l4[0], l4[2]}, bl1[2] = {l4[1], l4[3]};
#pragma unroll
                for (int mt = 0; mt < 2; mt++) {
                    mma16816h(acc[mt][2 * np],     ah[mt], bh0);
                    mma16816h(acc[mt][2 * np],     ah[mt], bl0);
                    mma16816h(acc[mt][2 * np + 1], ah[mt], bh1);
                    mma16816h(acc[mt][2 * np + 1], ah[mt], bl1);
                }
            }
        }
    }

    if (mode == 1) {
#pragma unroll
        for (int mt = 0; mt < 2; mt++) {
#pragma unroll
            for (int nt = 0; nt < 8; nt++) {
                int r = row0 + wm + mt * 16 + (lane >> 2);
                int c = col0 + wn + nt * 8 + (lane & 3) * 2;
                float b0 = bias[c], b1 = bias[c + 1];
                float2 v0 = {acc[mt][nt][0] + b0, acc[mt][nt][1] + b1};
                float2 v1 = {acc[mt][nt][2] + b0, acc[mt][nt][3] + b1};
                *reinterpret_cast<float2*>(Cf + (size_t)r * DIMM + c)       = v0;
                *reinterpret_cast<float2*>(Cf + (size_t)(r + 8) * DIMM + c) = v1;
            }
        }
    } else {
        __half* dst;
        float osc = 1.0f;
        int cb;
        if (col0 < 512)       { dst = Qd; cb = col0;        osc = QSCALE; }
        else if (col0 < 1024) { dst = Kd; cb = col0 - 512; }
        else                  { dst = Vd; cb = col0 - 1024; }
#pragma unroll
        for (int mt = 0; mt < 2; mt++) {
#pragma unroll
            for (int nt = 0; nt < 8; nt++) {
                int r = row0 + wm + mt * 16 + (lane >> 2);
                int c = cb + wn + nt * 8 + (lane & 3) * 2;
                *reinterpret_cast<uint32_t*>(dst + (size_t)r * DIMM + c) =
                    h2pack(acc[mt][nt][0] * osc, acc[mt][nt][1] * osc);
                *reinterpret_cast<uint32_t*>(dst + (size_t)(r + 8) * DIMM + c) =
                    h2pack(acc[mt][nt][2] * osc, acc[mt][nt][3] * osc);
            }
        }
    }
}

// ---------------------------------------------------------------------------
// fp16 HMMA flash attention, all-single precision: S = Q K^T, O += P V.
// 8 warps (m16 each), cp.async double-buffered K/V, exp2-domain softmax.
// ---------------------------------------------------------------------------
#define AP 72
#define KVST_B (2 * 64 * AP * 2)   // 18432 bytes per stage: K | V

__global__ void __launch_bounds__(256, 2) mma_attn_kernel(
    const __half* __restrict__ q, const __half* __restrict__ k,
    const __half* __restrict__ v,
    const float* __restrict__ mk, const float* __restrict__ mv,
    __half* __restrict__ og)
{
    extern __shared__ __half smh[];
    // layout: Q[128*AP] | stage0{K,V each 64*AP} | stage1{...}
    const int tid = threadIdx.x, wid = tid >> 5, lane = tid & 31;
    const int bh = blockIdx.y, b = bh >> 3, h = bh & 7;
    const int q0 = blockIdx.x * 128;
    const int bN = b * NTOK;
    const uint32_t base = smem_u32(smh);
    const uint32_t offKV = 128 * AP * 2;   // 18432

    // Load Q tile (fp16), 128x64
#pragma unroll
    for (int it = 0; it < 4; it++) {
        int i = tid + it * 256;
        int r = i >> 3, u = i & 7;
        size_t go = (size_t)(bN + q0 + r) * DIMM + h * DHD + u * 8;
        *reinterpret_cast<uint4*>(smh + r * AP + u * 8) = *reinterpret_cast<const uint4*>(q + go);
    }

    float o[8][4];
#pragma unroll
    for (int nt = 0; nt < 8; nt++)
#pragma unroll
        for (int j = 0; j < 4; j++) o[nt][j] = 0.0f;
    float mi[2] = {-1e30f, -1e30f};
    float li[2] = {0.f, 0.f};

    const int lr = lane & 15, lc = (lane >> 4) * 8;

    // Prologue: prefetch tile 0 into stage 0
    {
        const uint32_t kb = base + offKV;
#pragma unroll
        for (int it = 0; it < 2; it++) {
            int i = tid + it * 256;
            int r = i >> 3, u = i & 7;
            size_t gk = (size_t)(bN + r) * DIMM + h * DHD + u * 8;
            uint32_t d = kb + (uint32_t)((r * AP + u * 8) * 2);
            CP16(d,        k + gk);
            CP16(d + 9216, v + gk);
        }
        CP_COMMIT();
    }

    for (int t = 0; t < 33; t++) {
        const int stage = t & 1;

        if (t < 32) CP_WAIT0();
        __syncthreads();

        if (t + 1 < 32) {
            const uint32_t kb2 = base + offKV + (stage ^ 1) * KVST_B;
#pragma unroll
            for (int it = 0; it < 2; it++) {
                int i = tid + it * 256;
                int r = i >> 3, u = i & 7;
                size_t gk = (size_t)(bN + (t + 1) * 64 + r) * DIMM + h * DHD + u * 8;
                uint32_t d = kb2 + (uint32_t)((r * AP + u * 8) * 2);
                CP16(d,        k + gk);
                CP16(d + 9216, v + gk);
            }
            CP_COMMIT();
        }

        if (t == 32) {
            __half* skv = smh + 128 * AP;  // stage 0
            uint4 z = {0u, 0u, 0u, 0u};
#pragma unroll
            for (int it = 0; it < 5; it++) {
                int idx = tid + it * 256;
                if (idx < 1152) *(reinterpret_cast<uint4*>(skv) + idx) = z;
            }
            __syncthreads();
            if (tid < MTOK * 64) {
                int kk = tid >> 6, dd = tid & 63;
                int mi_ = h * (MTOK * DHD) + kk * DHD + dd;
                skv[kk * AP + dd]           = __float2half(SQRT_DH * mk[mi_]);
                skv[64 * AP + kk * AP + dd] = __float2half(SQRT_M  * mv[mi_]);
            }
            __syncthreads();
        }
        const uint32_t kbc = base + offKV + ((t == 32) ? 0 : stage * KVST_B);

        // ---- S = Q K^T ----
        float s[8][4];
#pragma unroll
        for (int nt = 0; nt < 8; nt++)
#pragma unroll
            for (int j = 0; j < 4; j++) s[nt][j] = 0.0f;

#pragma unroll
        for (int kt = 0; kt < 4; kt++) {
            uint32_t aq[4];
            ldsm4(aq, base + (uint32_t)(((wid * 16 + lr) * AP + kt * 16 + lc) * 2));
#pragma unroll
            for (int np = 0; np < 4; np++) {
                uint32_t r4[4];
                ldsm4(r4, kbc + (uint32_t)(((np * 16 + lr) * AP + kt * 16 + lc) * 2));
                uint32_t bh0[2] = {r4[0], r4[2]}, bh1[2] = {r4[1], r4[3]};
                mma16816h(s[2 * np],     aq, bh0);
                mma16816h(s[2 * np + 1], aq, bh1);
            }
        }

        if (t == 32) {
#pragma unroll
            for (int nt = 0; nt < 8; nt++) {
                int c0 = nt * 8 + (lane & 3) * 2;
                if (c0 >= MTOK)     { s[nt][0] = -1e30f; s[nt][2] = -1e30f; }
                if (c0 + 1 >= MTOK) { s[nt][1] = -1e30f; s[nt][3] = -1e30f; }
            }
        }

        // ---- online softmax (exp2 domain) ----
#pragma unroll
        for (int hh = 0; hh < 2; hh++) {
            float rm = -1e30f;
#pragma unroll
            for (int nt = 0; nt < 8; nt++) {
                rm = fmaxf(rm, s[nt][2 * hh]);
                rm = fmaxf(rm, s[nt][2 * hh + 1]);
            }
            rm = fmaxf(rm, __shfl_xor_sync(0xffffffffu, rm, 1));
            rm = fmaxf(rm, __shfl_xor_sync(0xffffffffu, rm, 2));
            float mold = mi[hh];
            float mn = fmaxf(mold, rm);
            float alpha = fast_exp2(mold - mn);
            float sum = 0.f;
#pragma unroll
            for (int nt = 0; nt < 8; nt++) {
                float p0 = fast_exp2(s[nt][2 * hh]     - mn);
                float p1 = fast_exp2(s[nt][2 * hh + 1] - mn);
                s[nt][2 * hh]     = p0;
                s[nt][2 * hh + 1] = p1;
                sum += p0 + p1;
            }
            sum += __shfl_xor_sync(0xffffffffu, sum, 1);
            sum += __shfl_xor_sync(0xffffffffu, sum, 2);
            li[hh] = li[hh] * alpha + sum;
            mi[hh] = mn;
            if (!__all_sync(0xffffffffu, mn == mold)) {
#pragma unroll
                for (int nt = 0; nt < 8; nt++) {
                    o[nt][2 * hh]     *= alpha;
                    o[nt][2 * hh + 1] *= alpha;
                }
            }
        }

        // ---- O += P V ----
#pragma unroll
        for (int kt = 0; kt < 4; kt++) {
            uint32_t ap_[4];
            ap_[0] = h2pack(s[2 * kt][0],     s[2 * kt][1]);
            ap_[1] = h2pack(s[2 * kt][2],     s[2 * kt][3]);
            ap_[2] = h2pack(s[2 * kt + 1][0], s[2 * kt + 1][1]);
            ap_[3] = h2pack(s[2 * kt + 1][2], s[2 * kt + 1][3]);
#pragma unroll
            for (int np = 0; np < 4; np++) {
                uint32_t r4[4];
                ldsm4t(r4, kbc + 9216 + (uint32_t)(((kt * 16 + lr) * AP + np * 16 + lc) * 2));
                uint32_t vh0[2] = {r4[0], r4[1]}, vh1[2] = {r4[2], r4[3]};
                mma16816h(o[2 * np],     ap_, vh0);
                mma16816h(o[2 * np + 1], ap_, vh1);
            }
        }
    }

    // ---- normalize + write single fp16 (feeds out-proj) ----
    float inv[2] = {__fdividef(1.0f, li[0]), __fdividef(1.0f, li[1])};

#pragma unroll
    for (int nt = 0; nt < 8; nt++) {
        int r = q0 + wid * 16 + (lane >> 2);
        int c = h * DHD + nt * 8 + (lane & 3) * 2;
        *reinterpret_cast<uint32_t*>(og + (size_t)(bN + r) * DIMM + c) =
            h2pack(o[nt][0] * inv[0], o[nt][1] * inv[0]);
        *reinterpret_cast<uint32_t*>(og + (size_t)(bN + r + 8) * DIMM + c) =
            h2pack(o[nt][2] * inv[1], o[nt][3] * inv[1]);
    }
}

// ---------------------------------------------------------------------------
extern "C" void kernel_launch(void* const* d_in, const int* in_sizes, int n_in,
                              void* d_out, int out_size)
{
    const float* x   = (const float*)d_in[0];
    const float* wq  = (const float*)d_in[1];
    const float* wkv = (const float*)d_in[2];
    const float* wo  = (const float*)d_in[3];
    const float* bo  = (const float*)d_in[4];
    const float* m_k = (const float*)d_in[5];
    const float* m_v = (const float*)d_in[6];
    float* out = (float*)d_out;

    __half *px, *pq, *pk, *pv, *po, *w3h, *w3l, *woh, *wol;
    cudaGetSymbolAddress((void**)&px,  g_x);
    cudaGetSymbolAddress((void**)&pq,  g_q);
    cudaGetSymbolAddress((void**)&pk,  g_k);
    cudaGetSymbolAddress((void**)&pv,  g_v);
    cudaGetSymbolAddress((void**)&po,  g_o);
    cudaGetSymbolAddress((void**)&w3h, g_w3h);
    cudaGetSymbolAddress((void**)&w3l, g_w3l);
    cudaGetSymbolAddress((void**)&woh, g_woh);
    cudaGetSymbolAddress((void**)&wol, g_wol);

    const int GEMM_SMEM = 2 * GST_B;              // 61440
    const int ATTN_SMEM = 128 * AP * 2 + 2 * KVST_B;  // 55296
    cudaFuncSetAttribute(mma_gemm_kernel, cudaFuncAttributeMaxDynamicSharedMemorySize, GEMM_SMEM);
    cudaFuncSetAttribute(mma_attn_kernel, cudaFuncAttributeMaxDynamicSharedMemorySize, ATTN_SMEM);

    // Prep
    convert_x_kernel<<<(MROWS * KDIM / 4 + 255) / 256, 256>>>(x, px, MROWS * KDIM);
    {
        dim3 grid(32, KDIM / 64);
        transpose_split_all<<<grid, 256>>>(wq, wkv, wo, w3h, w3l, woh, wol);
    }

    // Fused Q+K+V projection (N=1536), 2-term fp16
    {
        dim3 grid(3 * DIMM / 128, MROWS / 128);
        mma_gemm_kernel<<<grid, 256, GEMM_SMEM>>>(px, w3h, w3l,
            nullptr, nullptr, pq, pk, pv, 0);
    }
    // Attention (all-fp16 single)
    {
        dim3 grid(NTOK / 128, NB * NH);
        mma_attn_kernel<<<grid, 256, ATTN_SMEM>>>(pq, pk, pv, m_k, m_v, po);
    }
    // Output projection (+bias) -> fp32, 2-term fp16
    {
        dim3 grid(DIMM / 128, MROWS / 128);
        mma_gemm_kernel<<<grid, 256, GEMM_SMEM>>>(po, woh, wol,
            out, bo, nullptr, nullptr, nullptr, 1);
    }
}

// round 8
// speedup vs baseline: 7.4989x; 1.2792x over previous
#include <cuda_runtime.h>
#include <cuda_fp16.h>
#include <cstdint>

// Problem constants
#define NB    2
#define NTOK  2048
#define DIMM  512
#define NH    8
#define DHD   64
#define MTOK  3
#define SQRT_DH 8.0f
#define SQRT_M  1.7320508075688772f
#define SCALE   0.125f
#define LOG2E   1.4426950408889634f
#define QSCALE  (SCALE * LOG2E)
#define MROWS (NB * NTOK)   // 4096
#define KDIM  512

// ---------------------------------------------------------------------------
// Scratch
// ---------------------------------------------------------------------------
__device__ __half g_x[MROWS * KDIM];
__device__ __half g_q[MROWS * DIMM];
__device__ __half g_k[MROWS * DIMM];
__device__ __half g_v[MROWS * DIMM];
__device__ __half g_o[MROWS * DIMM];
__device__ __half g_w3[3 * DIMM * KDIM];   // [wq|wk|wv]^T fp16
__device__ __half g_wo[DIMM * KDIM];       // wo^T fp16

// ---------------------------------------------------------------------------
// Warp-MMA primitives
// ---------------------------------------------------------------------------
__device__ __forceinline__ uint32_t smem_u32(const void* p) {
    uint32_t a;
    asm("{ .reg .u64 t; cvta.to.shared.u64 t, %1; cvt.u32.u64 %0, t; }" : "=r"(a) : "l"(p));
    return a;
}
__device__ __forceinline__ void ldsm4(uint32_t* r, uint32_t a) {
    asm volatile("ldmatrix.sync.aligned.m8n8.x4.shared.b16 {%0,%1,%2,%3}, [%4];"
                 : "=r"(r[0]), "=r"(r[1]), "=r"(r[2]), "=r"(r[3]) : "r"(a));
}
__device__ __forceinline__ void ldsm4t(uint32_t* r, uint32_t a) {
    asm volatile("ldmatrix.sync.aligned.m8n8.x4.trans.shared.b16 {%0,%1,%2,%3}, [%4];"
                 : "=r"(r[0]), "=r"(r[1]), "=r"(r[2]), "=r"(r[3]) : "r"(a));
}
__device__ __forceinline__ void mma16816h(float* c, const uint32_t* a, const uint32_t* b) {
    asm volatile(
        "mma.sync.aligned.m16n8k16.row.col.f32.f16.f16.f32 "
        "{%0,%1,%2,%3}, {%4,%5,%6,%7}, {%8,%9}, {%0,%1,%2,%3};"
        : "+f"(c[0]), "+f"(c[1]), "+f"(c[2]), "+f"(c[3])
        : "r"(a[0]), "r"(a[1]), "r"(a[2]), "r"(a[3]), "r"(b[0]), "r"(b[1]));
}
#define CP16(dst, src) \
    asm volatile("cp.async.cg.shared.global [%0], [%1], 16;" :: "r"(dst), "l"(src))
#define CP_COMMIT() asm volatile("cp.async.commit_group;" ::: "memory")
#define CP_WAIT0()  asm volatile("cp.async.wait_group 0;" ::: "memory")

__device__ __forceinline__ float fast_exp2(float x) {
    float r;
    asm("ex2.approx.f32 %0, %1;" : "=f"(r) : "f"(x));
    return r;
}
// pack two fp32 into half2 (x -> lo, y -> hi)
__device__ __forceinline__ uint32_t cvt2h(float x, float y) {
    uint32_t r;
    asm("cvt.rn.f16x2.f32 %0, %1, %2;" : "=r"(r) : "f"(y), "f"(x));
    return r;
}
// 2-wide fp16 exp2 on MUFU
__device__ __forceinline__ uint32_t ex2_h2(uint32_t x) {
    uint32_t r;
    asm("ex2.approx.f16x2 %0, %1;" : "=r"(r) : "r"(x));
    return r;
}
__device__ __forceinline__ uint32_t h2pack(float x, float y) {
    __half2 v = __floats2half2_rn(x, y);
    return reinterpret_cast<uint32_t&>(v);
}

// ---------------------------------------------------------------------------
// Prep kernels
// ---------------------------------------------------------------------------
__global__ void __launch_bounds__(256) convert_x_kernel(
    const float* __restrict__ in, __half* __restrict__ outh, int n)
{
    int i = (blockIdx.x * 256 + threadIdx.x) * 4;
    if (i >= n) return;
    float4 v = *reinterpret_cast<const float4*>(in + i);
    uint2 o;
    o.x = h2pack(v.x, v.y);
    o.y = h2pack(v.z, v.w);
    *reinterpret_cast<uint2*>(outh + i) = o;
}

// Transpose+convert to single fp16: wq (N=512), wkv (N=1024), wo (N=512)
__global__ void __launch_bounds__(256) transpose_cvt_all(
    const float* __restrict__ wq, const float* __restrict__ wkv,
    const float* __restrict__ wo,
    __half* __restrict__ w3, __half* __restrict__ woT)
{
    __shared__ float tile[64][65];
    const int tid = threadIdx.x;
    const int ct = blockIdx.x;       // 0..31
    const int k0 = blockIdx.y * 64;

    const float* src;
    __half* dst;
    int N, n0, rowOff;
    if (ct < 8)       { src = wq;  N = 512;  n0 = ct * 64;        dst = w3;  rowOff = 0; }
    else if (ct < 24) { src = wkv; N = 1024; n0 = (ct - 8) * 64;  dst = w3;  rowOff = DIMM; }
    else              { src = wo;  N = 512;  n0 = (ct - 24) * 64; dst = woT; rowOff = 0; }

#pragma unroll
    for (int it = 0; it < 4; it++) {
        int idx = tid + it * 256;
        int r = idx >> 4, c4 = (idx & 15) * 4;
        float4 v = *reinterpret_cast<const float4*>(src + (size_t)(k0 + r) * N + n0 + c4);
        tile[r][c4 + 0] = v.x; tile[r][c4 + 1] = v.y;
        tile[r][c4 + 2] = v.z; tile[r][c4 + 3] = v.w;
    }
    __syncthreads();
#pragma unroll
    for (int it = 0; it < 4; it++) {
        int idx = tid + it * 256;
        int n = idx >> 4, kg = idx & 15;
        float v0 = tile[kg * 4 + 0][n], v1 = tile[kg * 4 + 1][n];
        float v2 = tile[kg * 4 + 2][n], v3 = tile[kg * 4 + 3][n];
        size_t d = (size_t)(rowOff + n0 + n) * KDIM + k0 + kg * 4;
        *reinterpret_cast<uint2*>(dst + d) = make_uint2(h2pack(v0, v1), h2pack(v2, v3));
    }
}

// ---------------------------------------------------------------------------
// fp16 HMMA GEMM, single-term: C = A @ B (fp16 x fp16, fp32 accum).
// CTA 128x128, 8 warps, BK=32 x 16 chunks, 2-stage cp.async pipeline.
// mode 0: fused QKV epilogue (Q*QSCALE / K / V fp16); mode 1: fp32 + bias.
// ---------------------------------------------------------------------------
#define GPAD 40
#define GST_B (2 * 128 * GPAD * 2)   // 20480 bytes per stage: A | B

__global__ void __launch_bounds__(256, 2) mma_gemm_kernel(
    const __half* __restrict__ A, const __half* __restrict__ BT,
    float* __restrict__ Cf, const float* __restrict__ bias,
    __half* __restrict__ Qd, __half* __restrict__ Kd, __half* __restrict__ Vd,
    int mode)
{
    extern __shared__ __half sg[];
    const int tid = threadIdx.x, wid = tid >> 5, lane = tid & 31;
    const int row0 = blockIdx.y * 128, col0 = blockIdx.x * 128;
    const int wm = (wid & 3) * 32, wn = (wid >> 2) * 64;
    const uint32_t base = smem_u32(sg);
    const int lr = lane & 15, lc = (lane >> 4) * 8;

    float acc[2][8][4];
#pragma unroll
    for (int mt = 0; mt < 2; mt++)
#pragma unroll
        for (int nt = 0; nt < 8; nt++)
#pragma unroll
            for (int j = 0; j < 4; j++) acc[mt][nt][j] = 0.0f;

    auto prefetch = [&](int c, int st) {
        int k0 = c * 32;
        uint32_t sb = base + st * GST_B;
#pragma unroll
        for (int it = 0; it < 2; it++) {
            int i = tid + it * 256;        // 0..511
            int r = i >> 2, u = i & 3;     // 128 rows x 4 16B-units
            size_t ga = (size_t)(row0 + r) * KDIM + k0 + u * 8;
            size_t gb = (size_t)(col0 + r) * KDIM + k0 + u * 8;
            uint32_t d = sb + (uint32_t)((r * GPAD + u * 8) * 2);
            CP16(d,         A + ga);
            CP16(d + 10240, BT + gb);
        }
    };

    prefetch(0, 0);
    CP_COMMIT();

    for (int c = 0; c < 16; c++) {
        CP_WAIT0();
        __syncthreads();
        if (c + 1 < 16) { prefetch(c + 1, (c + 1) & 1); CP_COMMIT(); }

        uint32_t sb = base + (c & 1) * GST_B;
#pragma unroll
        for (int kt = 0; kt < 2; kt++) {
            uint32_t ah[2][4];
#pragma unroll
            for (int mt = 0; mt < 2; mt++)
                ldsm4(ah[mt], sb + (uint32_t)(((wm + mt * 16 + lr) * GPAD + kt * 16 + lc) * 2));
#pragma unroll
            for (int np = 0; np < 4; np++) {
                uint32_t r4[4];
                ldsm4(r4, sb + 10240 + (uint32_t)(((wn + np * 16 + lr) * GPAD + kt * 16 + lc) * 2));
                uint32_t bh0[2] = {r4[0], r4[2]}, bh1[2] = {r4[1], r4[3]};
#pragma unroll
                for (int mt = 0; mt < 2; mt++) {
                    mma16816h(acc[mt][2 * np],     ah[mt], bh0);
                    mma16816h(acc[mt][2 * np + 1], ah[mt], bh1);
                }
            }
        }
    }

    if (mode == 1) {
#pragma unroll
        for (int mt = 0; mt < 2; mt++) {
#pragma unroll
            for (int nt = 0; nt < 8; nt++) {
                int r = row0 + wm + mt * 16 + (lane >> 2);
                int c = col0 + wn + nt * 8 + (lane & 3) * 2;
                float b0 = bias[c], b1 = bias[c + 1];
                float2 v0 = {acc[mt][nt][0] + b0, acc[mt][nt][1] + b1};
                float2 v1 = {acc[mt][nt][2] + b0, acc[mt][nt][3] + b1};
                *reinterpret_cast<float2*>(Cf + (size_t)r * DIMM + c)       = v0;
                *reinterpret_cast<float2*>(Cf + (size_t)(r + 8) * DIMM + c) = v1;
            }
        }
    } else {
        __half* dst;
        float osc = 1.0f;
        int cb;
        if (col0 < 512)       { dst = Qd; cb = col0;        osc = QSCALE; }
        else if (col0 < 1024) { dst = Kd; cb = col0 - 512; }
        else                  { dst = Vd; cb = col0 - 1024; }
#pragma unroll
        for (int mt = 0; mt < 2; mt++) {
#pragma unroll
            for (int nt = 0; nt < 8; nt++) {
                int r = row0 + wm + mt * 16 + (lane >> 2);
                int c = cb + wn + nt * 8 + (lane & 3) * 2;
                *reinterpret_cast<uint32_t*>(dst + (size_t)r * DIMM + c) =
                    h2pack(acc[mt][nt][0] * osc, acc[mt][nt][1] * osc);
                *reinterpret_cast<uint32_t*>(dst + (size_t)(r + 8) * DIMM + c) =
                    h2pack(acc[mt][nt][2] * osc, acc[mt][nt][3] * osc);
            }
        }
    }
}

// ---------------------------------------------------------------------------
// fp16 HMMA flash attention. 8 warps (m16 each), cp.async double-buffered K/V.
// exp2-domain softmax with f16x2 MUFU; row-sums via ones-MMA.
// ---------------------------------------------------------------------------
#define AP 72
#define KVST_B (2 * 64 * AP * 2)   // 18432 bytes per stage: K | V

__global__ void __launch_bounds__(256, 2) mma_attn_kernel(
    const __half* __restrict__ q, const __half* __restrict__ k,
    const __half* __restrict__ v,
    const float* __restrict__ mk, const float* __restrict__ mv,
    __half* __restrict__ og)
{
    extern __shared__ __half smh[];
    // layout: Q[128*AP] | stage0{K,V each 64*AP} | stage1{...}
    const int tid = threadIdx.x, wid = tid >> 5, lane = tid & 31;
    const int bh = blockIdx.y, b = bh >> 3, h = bh & 7;
    const int q0 = blockIdx.x * 128;
    const int bN = b * NTOK;
    const uint32_t base = smem_u32(smh);
    const uint32_t offKV = 128 * AP * 2;   // 18432

    // Load Q tile (fp16), 128x64
#pragma unroll
    for (int it = 0; it < 4; it++) {
        int i = tid + it * 256;
        int r = i >> 3, u = i & 7;
        size_t go = (size_t)(bN + q0 + r) * DIMM + h * DHD + u * 8;
        *reinterpret_cast<uint4*>(smh + r * AP + u * 8) = *reinterpret_cast<const uint4*>(q + go);
    }

    float o[8][4];
#pragma unroll
    for (int nt = 0; nt < 8; nt++)
#pragma unroll
        for (int j = 0; j < 4; j++) o[nt][j] = 0.0f;
    float mi[2] = {-1e30f, -1e30f};
    float li[2] = {0.f, 0.f};

    const int lr = lane & 15, lc = (lane >> 4) * 8;
    const uint32_t ones2[2] = {0x3C003C00u, 0x3C003C00u};

    // Prologue: prefetch tile 0 into stage 0
    {
        const uint32_t kb = base + offKV;
#pragma unroll
        for (int it = 0; it < 2; it++) {
            int i = tid + it * 256;
            int r = i >> 3, u = i & 7;
            size_t gk = (size_t)(bN + r) * DIMM + h * DHD + u * 8;
            uint32_t d = kb + (uint32_t)((r * AP + u * 8) * 2);
            CP16(d,        k + gk);
            CP16(d + 9216, v + gk);
        }
        CP_COMMIT();
    }

    for (int t = 0; t < 33; t++) {
        const int stage = t & 1;

        if (t < 32) CP_WAIT0();
        __syncthreads();

        if (t + 1 < 32) {
            const uint32_t kb2 = base + offKV + (stage ^ 1) * KVST_B;
#pragma unroll
            for (int it = 0; it < 2; it++) {
                int i = tid + it * 256;
                int r = i >> 3, u = i & 7;
                size_t gk = (size_t)(bN + (t + 1) * 64 + r) * DIMM + h * DHD + u * 8;
                uint32_t d = kb2 + (uint32_t)((r * AP + u * 8) * 2);
                CP16(d,        k + gk);
                CP16(d + 9216, v + gk);
            }
            CP_COMMIT();
        }

        if (t == 32) {
            __half* skv = smh + 128 * AP;  // stage 0
            uint4 z = {0u, 0u, 0u, 0u};
#pragma unroll
            for (int it = 0; it < 5; it++) {
                int idx = tid + it * 256;
                if (idx < 1152) *(reinterpret_cast<uint4*>(skv) + idx) = z;
            }
            __syncthreads();
            if (tid < MTOK * 64) {
                int kk = tid >> 6, dd = tid & 63;
                int mi_ = h * (MTOK * DHD) + kk * DHD + dd;
                skv[kk * AP + dd]           = __float2half(SQRT_DH * mk[mi_]);
                skv[64 * AP + kk * AP + dd] = __float2half(SQRT_M  * mv[mi_]);
            }
            __syncthreads();
        }
        const uint32_t kbc = base + offKV + ((t == 32) ? 0 : stage * KVST_B);

        // ---- S = Q K^T ----
        float s[8][4];
#pragma unroll
        for (int nt = 0; nt < 8; nt++)
#pragma unroll
            for (int j = 0; j < 4; j++) s[nt][j] = 0.0f;

#pragma unroll
        for (int kt = 0; kt < 4; kt++) {
            uint32_t aq[4];
            ldsm4(aq, base + (uint32_t)(((wid * 16 + lr) * AP + kt * 16 + lc) * 2));
#pragma unroll
            for (int np = 0; np < 4; np++) {
                uint32_t r4[4];
                ldsm4(r4, kbc + (uint32_t)(((np * 16 + lr) * AP + kt * 16 + lc) * 2));
                uint32_t bh0[2] = {r4[0], r4[2]}, bh1[2] = {r4[1], r4[3]};
                mma16816h(s[2 * np],     aq, bh0);
                mma16816h(s[2 * np + 1], aq, bh1);
            }
        }

        if (t == 32) {
#pragma unroll
            for (int nt = 0; nt < 8; nt++) {
                int c0 = nt * 8 + (lane & 3) * 2;
                if (c0 >= MTOK)     { s[nt][0] = -1e30f; s[nt][2] = -1e30f; }
                if (c0 + 1 >= MTOK) { s[nt][1] = -1e30f; s[nt][3] = -1e30f; }
            }
        }

        // ---- online softmax: max reduce (fp32) ----
        float mn01[2], alpha01[2];
#pragma unroll
        for (int hh = 0; hh < 2; hh++) {
            float rm = -1e30f;
#pragma unroll
            for (int nt = 0; nt < 8; nt++) {
                rm = fmaxf(rm, s[nt][2 * hh]);
                rm = fmaxf(rm, s[nt][2 * hh + 1]);
            }
            rm = fmaxf(rm, __shfl_xor_sync(0xffffffffu, rm, 1));
            rm = fmaxf(rm, __shfl_xor_sync(0xffffffffu, rm, 2));
            float mold = mi[hh];
            float mn = fmaxf(mold, rm);
            mn01[hh] = mn;
            alpha01[hh] = fast_exp2(mold - mn);
            mi[hh] = mn;
            if (!__all_sync(0xffffffffu, mn == mold)) {
                float a = alpha01[hh];
#pragma unroll
                for (int nt = 0; nt < 8; nt++) {
                    o[nt][2 * hh]     *= a;
                    o[nt][2 * hh + 1] *= a;
                }
            }
        }

        // ---- P = exp2(S - mn), f16x2 MUFU, already packed for MMA ----
        uint32_t ph[8][2];
#pragma unroll
        for (int nt = 0; nt < 8; nt++) {
            ph[nt][0] = ex2_h2(cvt2h(s[nt][0] - mn01[0], s[nt][1] - mn01[0]));
            ph[nt][1] = ex2_h2(cvt2h(s[nt][2] - mn01[1], s[nt][3] - mn01[1]));
        }

        // ---- lsum (rowsums via ones-MMA) + O += P V ----
        float ls[4] = {0.f, 0.f, 0.f, 0.f};
#pragma unroll
        for (int kt = 0; kt < 4; kt++) {
            uint32_t ap_[4] = {ph[2 * kt][0], ph[2 * kt][1],
                               ph[2 * kt + 1][0], ph[2 * kt + 1][1]};
            mma16816h(ls, ap_, ones2);
#pragma unroll
            for (int np = 0; np < 4; np++) {
                uint32_t r4[4];
                ldsm4t(r4, kbc + 9216 + (uint32_t)(((kt * 16 + lr) * AP + np * 16 + lc) * 2));
                uint32_t vh0[2] = {r4[0], r4[1]}, vh1[2] = {r4[2], r4[3]};
                mma16816h(o[2 * np],     ap_, vh0);
                mma16816h(o[2 * np + 1], ap_, vh1);
            }
        }
        li[0] = li[0] * alpha01[0] + ls[0];
        li[1] = li[1] * alpha01[1] + ls[2];
    }

    // ---- normalize + write single fp16 (feeds out-proj) ----
    float inv[2] = {__fdividef(1.0f, li[0]), __fdividef(1.0f, li[1])};

#pragma unroll
    for (int nt = 0; nt < 8; nt++) {
        int r = q0 + wid * 16 + (lane >> 2);
        int c = h * DHD + nt * 8 + (lane & 3) * 2;
        *reinterpret_cast<uint32_t*>(og + (size_t)(bN + r) * DIMM + c) =
            h2pack(o[nt][0] * inv[0], o[nt][1] * inv[0]);
        *reinterpret_cast<uint32_t*>(og + (size_t)(bN + r + 8) * DIMM + c) =
            h2pack(o[nt][2] * inv[1], o[nt][3] * inv[1]);
    }
}

// ---------------------------------------------------------------------------
extern "C" void kernel_launch(void* const* d_in, const int* in_sizes, int n_in,
                              void* d_out, int out_size)
{
    const float* x   = (const float*)d_in[0];
    const float* wq  = (const float*)d_in[1];
    const float* wkv = (const float*)d_in[2];
    const float* wo  = (const float*)d_in[3];
    const float* bo  = (const float*)d_in[4];
    const float* m_k = (const float*)d_in[5];
    const float* m_v = (const float*)d_in[6];
    float* out = (float*)d_out;

    __half *px, *pq, *pk, *pv, *po, *pw3, *pwo;
    cudaGetSymbolAddress((void**)&px,  g_x);
    cudaGetSymbolAddress((void**)&pq,  g_q);
    cudaGetSymbolAddress((void**)&pk,  g_k);
    cudaGetSymbolAddress((void**)&pv,  g_v);
    cudaGetSymbolAddress((void**)&po,  g_o);
    cudaGetSymbolAddress((void**)&pw3, g_w3);
    cudaGetSymbolAddress((void**)&pwo, g_wo);

    const int GEMM_SMEM = 2 * GST_B;                 // 40960
    const int ATTN_SMEM = 128 * AP * 2 + 2 * KVST_B; // 55296
    cudaFuncSetAttribute(mma_gemm_kernel, cudaFuncAttributeMaxDynamicSharedMemorySize, GEMM_SMEM);
    cudaFuncSetAttribute(mma_attn_kernel, cudaFuncAttributeMaxDynamicSharedMemorySize, ATTN_SMEM);

    // Prep
    convert_x_kernel<<<(MROWS * KDIM / 4 + 255) / 256, 256>>>(x, px, MROWS * KDIM);
    {
        dim3 grid(32, KDIM / 64);
        transpose_cvt_all<<<grid, 256>>>(wq, wkv, wo, pw3, pwo);
    }

    // Fused Q+K+V projection (N=1536), single-term fp16
    {
        dim3 grid(3 * DIMM / 128, MROWS / 128);
        mma_gemm_kernel<<<grid, 256, GEMM_SMEM>>>(px, pw3,
            nullptr, nullptr, pq, pk, pv, 0);
    }
    // Attention
    {
        dim3 grid(NTOK / 128, NB * NH);
        mma_attn_kernel<<<grid, 256, ATTN_SMEM>>>(pq, pk, pv, m_k, m_v, po);
    }
    // Output projection (+bias) -> fp32
    {
        dim3 grid(DIMM / 128, MROWS / 128);
        mma_gemm_kernel<<<grid, 256, GEMM_SMEM>>>(po, pwo,
            out, bo, nullptr, nullptr, nullptr, 1);
    }
}

// round 9
// speedup vs baseline: 7.8343x; 1.0447x over previous
#include <cuda_runtime.h>
#include <cuda_fp16.h>
#include <cstdint>

// Problem constants
#define NB    2
#define NTOK  2048
#define DIMM  512
#define NH    8
#define DHD   64
#define MTOK  3
#define SQRT_DH 8.0f
#define SQRT_M  1.7320508075688772f
#define SCALE   0.125f
#define LOG2E   1.4426950408889634f
#define QSCALE  (SCALE * LOG2E)
#define MROWS (NB * NTOK)   // 4096
#define KDIM  512

// ---------------------------------------------------------------------------
// Scratch
// ---------------------------------------------------------------------------
__device__ __half g_x[MROWS * KDIM];
__device__ __half g_q[MROWS * DIMM];
__device__ __half g_k[MROWS * DIMM];
__device__ __half g_v[MROWS * DIMM];
__device__ __half g_o[MROWS * DIMM];
__device__ __half g_w3[3 * DIMM * KDIM];   // [wq|wk|wv]^T fp16
__device__ __half g_wo[DIMM * KDIM];       // wo^T fp16

// ---------------------------------------------------------------------------
// Warp-MMA primitives
// ---------------------------------------------------------------------------
__device__ __forceinline__ uint32_t smem_u32(const void* p) {
    uint32_t a;
    asm("{ .reg .u64 t; cvta.to.shared.u64 t, %1; cvt.u32.u64 %0, t; }" : "=r"(a) : "l"(p));
    return a;
}
__device__ __forceinline__ void ldsm4(uint32_t* r, uint32_t a) {
    asm volatile("ldmatrix.sync.aligned.m8n8.x4.shared.b16 {%0,%1,%2,%3}, [%4];"
                 : "=r"(r[0]), "=r"(r[1]), "=r"(r[2]), "=r"(r[3]) : "r"(a));
}
__device__ __forceinline__ void ldsm4t(uint32_t* r, uint32_t a) {
    asm volatile("ldmatrix.sync.aligned.m8n8.x4.trans.shared.b16 {%0,%1,%2,%3}, [%4];"
                 : "=r"(r[0]), "=r"(r[1]), "=r"(r[2]), "=r"(r[3]) : "r"(a));
}
__device__ __forceinline__ void mma16816h(float* c, const uint32_t* a, const uint32_t* b) {
    asm volatile(
        "mma.sync.aligned.m16n8k16.row.col.f32.f16.f16.f32 "
        "{%0,%1,%2,%3}, {%4,%5,%6,%7}, {%8,%9}, {%0,%1,%2,%3};"
        : "+f"(c[0]), "+f"(c[1]), "+f"(c[2]), "+f"(c[3])
        : "r"(a[0]), "r"(a[1]), "r"(a[2]), "r"(a[3]), "r"(b[0]), "r"(b[1]));
}
#define CP16(dst, src) \
    asm volatile("cp.async.cg.shared.global [%0], [%1], 16;" :: "r"(dst), "l"(src))
#define CP_COMMIT() asm volatile("cp.async.commit_group;" ::: "memory")
#define CP_WAIT0()  asm volatile("cp.async.wait_group 0;" ::: "memory")

__device__ __forceinline__ float fast_exp2(float x) {
    float r;
    asm("ex2.approx.f32 %0, %1;" : "=f"(r) : "f"(x));
    return r;
}
// pack two fp32 into half2 (x -> lo, y -> hi)
__device__ __forceinline__ uint32_t cvt2h(float x, float y) {
    uint32_t r;
    asm("cvt.rn.f16x2.f32 %0, %1, %2;" : "=r"(r) : "f"(y), "f"(x));
    return r;
}
// 2-wide fp16 exp2 on MUFU
__device__ __forceinline__ uint32_t ex2_h2(uint32_t x) {
    uint32_t r;
    asm("ex2.approx.f16x2 %0, %1;" : "=r"(r) : "r"(x));
    return r;
}
__device__ __forceinline__ uint32_t h2pack(float x, float y) {
    __half2 v = __floats2half2_rn(x, y);
    return reinterpret_cast<uint32_t&>(v);
}

// ---------------------------------------------------------------------------
// Prep kernels
// ---------------------------------------------------------------------------
__global__ void __launch_bounds__(256) convert_x_kernel(
    const float* __restrict__ in, __half* __restrict__ outh, int n)
{
    int i = (blockIdx.x * 256 + threadIdx.x) * 4;
    if (i >= n) return;
    float4 v = *reinterpret_cast<const float4*>(in + i);
    uint2 o;
    o.x = h2pack(v.x, v.y);
    o.y = h2pack(v.z, v.w);
    *reinterpret_cast<uint2*>(outh + i) = o;
}

// Transpose+convert to single fp16: wq (N=512), wkv (N=1024), wo (N=512)
__global__ void __launch_bounds__(256) transpose_cvt_all(
    const float* __restrict__ wq, const float* __restrict__ wkv,
    const float* __restrict__ wo,
    __half* __restrict__ w3, __half* __restrict__ woT)
{
    __shared__ float tile[64][65];
    const int tid = threadIdx.x;
    const int ct = blockIdx.x;       // 0..31
    const int k0 = blockIdx.y * 64;

    const float* src;
    __half* dst;
    int N, n0, rowOff;
    if (ct < 8)       { src = wq;  N = 512;  n0 = ct * 64;        dst = w3;  rowOff = 0; }
    else if (ct < 24) { src = wkv; N = 1024; n0 = (ct - 8) * 64;  dst = w3;  rowOff = DIMM; }
    else              { src = wo;  N = 512;  n0 = (ct - 24) * 64; dst = woT; rowOff = 0; }

#pragma unroll
    for (int it = 0; it < 4; it++) {
        int idx = tid + it * 256;
        int r = idx >> 4, c4 = (idx & 15) * 4;
        float4 v = *reinterpret_cast<const float4*>(src + (size_t)(k0 + r) * N + n0 + c4);
        tile[r][c4 + 0] = v.x; tile[r][c4 + 1] = v.y;
        tile[r][c4 + 2] = v.z; tile[r][c4 + 3] = v.w;
    }
    __syncthreads();
#pragma unroll
    for (int it = 0; it < 4; it++) {
        int idx = tid + it * 256;
        int n = idx >> 4, kg = idx & 15;
        float v0 = tile[kg * 4 + 0][n], v1 = tile[kg * 4 + 1][n];
        float v2 = tile[kg * 4 + 2][n], v3 = tile[kg * 4 + 3][n];
        size_t d = (size_t)(rowOff + n0 + n) * KDIM + k0 + kg * 4;
        *reinterpret_cast<uint2*>(dst + d) = make_uint2(h2pack(v0, v1), h2pack(v2, v3));
    }
}

// ---------------------------------------------------------------------------
// fp16 HMMA GEMM: C = A @ B. CTA 128x128, 8 warps, BK=64 x 8 chunks,
// 2-stage cp.async pipeline.
// mode 0: fused QKV epilogue (Q*QSCALE / K / V fp16); mode 1: fp32 + bias.
// ---------------------------------------------------------------------------
#define GPAD 72
#define GST_B (2 * 128 * GPAD * 2)   // 36864 bytes per stage: A | B

__global__ void __launch_bounds__(256, 2) mma_gemm_kernel(
    const __half* __restrict__ A, const __half* __restrict__ BT,
    float* __restrict__ Cf, const float* __restrict__ bias,
    __half* __restrict__ Qd, __half* __restrict__ Kd, __half* __restrict__ Vd,
    int mode)
{
    extern __shared__ __half sg[];
    const int tid = threadIdx.x, wid = tid >> 5, lane = tid & 31;
    const int row0 = blockIdx.y * 128, col0 = blockIdx.x * 128;
    const int wm = (wid & 3) * 32, wn = (wid >> 2) * 64;
    const uint32_t base = smem_u32(sg);
    const int lr = lane & 15, lc = (lane >> 4) * 8;

    float acc[2][8][4];
#pragma unroll
    for (int mt = 0; mt < 2; mt++)
#pragma unroll
        for (int nt = 0; nt < 8; nt++)
#pragma unroll
            for (int j = 0; j < 4; j++) acc[mt][nt][j] = 0.0f;

    auto prefetch = [&](int c, int st) {
        int k0 = c * 64;
        uint32_t sb = base + st * GST_B;
#pragma unroll
        for (int it = 0; it < 4; it++) {
            int i = tid + it * 256;        // 0..1023
            int r = i >> 3, u = i & 7;     // 128 rows x 8 16B-units
            size_t ga = (size_t)(row0 + r) * KDIM + k0 + u * 8;
            size_t gb = (size_t)(col0 + r) * KDIM + k0 + u * 8;
            uint32_t d = sb + (uint32_t)((r * GPAD + u * 8) * 2);
            CP16(d,         A + ga);
            CP16(d + 18432, BT + gb);
        }
    };

    prefetch(0, 0);
    CP_COMMIT();

    for (int c = 0; c < 8; c++) {
        CP_WAIT0();
        __syncthreads();
        if (c + 1 < 8) { prefetch(c + 1, (c + 1) & 1); CP_COMMIT(); }

        uint32_t sb = base + (c & 1) * GST_B;
#pragma unroll
        for (int kt = 0; kt < 4; kt++) {
            uint32_t ah[2][4];
#pragma unroll
            for (int mt = 0; mt < 2; mt++)
                ldsm4(ah[mt], sb + (uint32_t)(((wm + mt * 16 + lr) * GPAD + kt * 16 + lc) * 2));
#pragma unroll
            for (int np = 0; np < 4; np++) {
                uint32_t r4[4];
                ldsm4(r4, sb + 18432 + (uint32_t)(((wn + np * 16 + lr) * GPAD + kt * 16 + lc) * 2));
                uint32_t bh0[2] = {r4[0], r4[2]}, bh1[2] = {r4[1], r4[3]};
#pragma unroll
                for (int mt = 0; mt < 2; mt++) {
                    mma16816h(acc[mt][2 * np],     ah[mt], bh0);
                    mma16816h(acc[mt][2 * np + 1], ah[mt], bh1);
                }
            }
        }
    }

    if (mode == 1) {
#pragma unroll
        for (int mt = 0; mt < 2; mt++) {
#pragma unroll
            for (int nt = 0; nt < 8; nt++) {
                int r = row0 + wm + mt * 16 + (lane >> 2);
                int c = col0 + wn + nt * 8 + (lane & 3) * 2;
                float b0 = bias[c], b1 = bias[c + 1];
                float2 v0 = {acc[mt][nt][0] + b0, acc[mt][nt][1] + b1};
                float2 v1 = {acc[mt][nt][2] + b0, acc[mt][nt][3] + b1};
                *reinterpret_cast<float2*>(Cf + (size_t)r * DIMM + c)       = v0;
                *reinterpret_cast<float2*>(Cf + (size_t)(r + 8) * DIMM + c) = v1;
            }
        }
    } else {
        __half* dst;
        float osc = 1.0f;
        int cb;
        if (col0 < 512)       { dst = Qd; cb = col0;        osc = QSCALE; }
        else if (col0 < 1024) { dst = Kd; cb = col0 - 512; }
        else                  { dst = Vd; cb = col0 - 1024; }
#pragma unroll
        for (int mt = 0; mt < 2; mt++) {
#pragma unroll
            for (int nt = 0; nt < 8; nt++) {
                int r = row0 + wm + mt * 16 + (lane >> 2);
                int c = cb + wn + nt * 8 + (lane & 3) * 2;
                *reinterpret_cast<uint32_t*>(dst + (size_t)r * DIMM + c) =
                    h2pack(acc[mt][nt][0] * osc, acc[mt][nt][1] * osc);
                *reinterpret_cast<uint32_t*>(dst + (size_t)(r + 8) * DIMM + c) =
                    h2pack(acc[mt][nt][2] * osc, acc[mt][nt][3] * osc);
            }
        }
    }
}

// ---------------------------------------------------------------------------
// fp16 HMMA flash attention. 4 warps (m32 x n64 each), cp.async 2-stage K/V.
// K/V fragments reused across the two m16 sub-tiles (halved LDSM traffic).
// exp2-domain softmax with f16x2 MUFU; row-sums via ones-MMA.
// ---------------------------------------------------------------------------
#define AP 72
#define KVST_B (2 * 64 * AP * 2)   // 18432 bytes per stage: K | V

__global__ void __launch_bounds__(128, 3) mma_attn_kernel(
    const __half* __restrict__ q, const __half* __restrict__ k,
    const __half* __restrict__ v,
    const float* __restrict__ mk, const float* __restrict__ mv,
    __half* __restrict__ og)
{
    extern __shared__ __half smh[];
    // layout: Q[128*AP] | stage0{K,V each 64*AP} | stage1{...}
    const int tid = threadIdx.x, wid = tid >> 5, lane = tid & 31;
    const int bh = blockIdx.y, b = bh >> 3, h = bh & 7;
    const int q0 = blockIdx.x * 128;
    const int bN = b * NTOK;
    const uint32_t base = smem_u32(smh);
    const uint32_t offKV = 128 * AP * 2;   // 18432

    // Load Q tile (fp16), 128x64
#pragma unroll
    for (int it = 0; it < 8; it++) {
        int i = tid + it * 128;
        int r = i >> 3, u = i & 7;
        size_t go = (size_t)(bN + q0 + r) * DIMM + h * DHD + u * 8;
        *reinterpret_cast<uint4*>(smh + r * AP + u * 8) = *reinterpret_cast<const uint4*>(q + go);
    }

    float o[2][8][4];
#pragma unroll
    for (int mt = 0; mt < 2; mt++)
#pragma unroll
        for (int nt = 0; nt < 8; nt++)
#pragma unroll
            for (int j = 0; j < 4; j++) o[mt][nt][j] = 0.0f;
    float mi[2][2] = {{-1e30f, -1e30f}, {-1e30f, -1e30f}};
    float li[2][2] = {{0.f, 0.f}, {0.f, 0.f}};

    const int lr = lane & 15, lc = (lane >> 4) * 8;
    const uint32_t ones2[2] = {0x3C003C00u, 0x3C003C00u};

    // Prologue: prefetch tile 0 into stage 0
    {
        const uint32_t kb = base + offKV;
#pragma unroll
        for (int it = 0; it < 4; it++) {
            int i = tid + it * 128;
            int r = i >> 3, u = i & 7;
            size_t gk = (size_t)(bN + r) * DIMM + h * DHD + u * 8;
            uint32_t d = kb + (uint32_t)((r * AP + u * 8) * 2);
            CP16(d,        k + gk);
            CP16(d + 9216, v + gk);
        }
        CP_COMMIT();
    }

    for (int t = 0; t < 33; t++) {
        const int stage = t & 1;

        if (t < 32) CP_WAIT0();
        __syncthreads();

        if (t + 1 < 32) {
            const uint32_t kb2 = base + offKV + (stage ^ 1) * KVST_B;
#pragma unroll
            for (int it = 0; it < 4; it++) {
                int i = tid + it * 128;
                int r = i >> 3, u = i & 7;
                size_t gk = (size_t)(bN + (t + 1) * 64 + r) * DIMM + h * DHD + u * 8;
                uint32_t d = kb2 + (uint32_t)((r * AP + u * 8) * 2);
                CP16(d,        k + gk);
                CP16(d + 9216, v + gk);
            }
            CP_COMMIT();
        }

        if (t == 32) {
            __half* skv = smh + 128 * AP;  // stage 0
            uint4 z = {0u, 0u, 0u, 0u};
#pragma unroll
            for (int it = 0; it < 9; it++)
                *(reinterpret_cast<uint4*>(skv) + tid + it * 128) = z;
            __syncthreads();
            for (int idx = tid; idx < MTOK * 64; idx += 128) {
                int kk = idx >> 6, dd = idx & 63;
                int mi_ = h * (MTOK * DHD) + kk * DHD + dd;
                skv[kk * AP + dd]           = __float2half(SQRT_DH * mk[mi_]);
                skv[64 * AP + kk * AP + dd] = __float2half(SQRT_M  * mv[mi_]);
            }
            __syncthreads();
        }
        const uint32_t kbc = base + offKV + ((t == 32) ? 0 : stage * KVST_B);

        // ---- S = Q K^T (m32 x n64 per warp; K frags shared across mt) ----
        float s[2][8][4];
#pragma unroll
        for (int mt = 0; mt < 2; mt++)
#pragma unroll
            for (int nt = 0; nt < 8; nt++)
#pragma unroll
                for (int j = 0; j < 4; j++) s[mt][nt][j] = 0.0f;

#pragma unroll
        for (int kt = 0; kt < 4; kt++) {
            uint32_t aq[2][4];
#pragma unroll
            for (int mt = 0; mt < 2; mt++)
                ldsm4(aq[mt], base + (uint32_t)(((wid * 32 + mt * 16 + lr) * AP + kt * 16 + lc) * 2));
#pragma unroll
            for (int np = 0; np < 4; np++) {
                uint32_t r4[4];
                ldsm4(r4, kbc + (uint32_t)(((np * 16 + lr) * AP + kt * 16 + lc) * 2));
                uint32_t bh0[2] = {r4[0], r4[2]}, bh1[2] = {r4[1], r4[3]};
#pragma unroll
                for (int mt = 0; mt < 2; mt++) {
                    mma16816h(s[mt][2 * np],     aq[mt], bh0);
                    mma16816h(s[mt][2 * np + 1], aq[mt], bh1);
                }
            }
        }

        if (t == 32) {
#pragma unroll
            for (int nt = 0; nt < 8; nt++) {
                int c0 = nt * 8 + (lane & 3) * 2;
                if (c0 >= MTOK) {
#pragma unroll
                    for (int mt = 0; mt < 2; mt++) { s[mt][nt][0] = -1e30f; s[mt][nt][2] = -1e30f; }
                }
                if (c0 + 1 >= MTOK) {
#pragma unroll
                    for (int mt = 0; mt < 2; mt++) { s[mt][nt][1] = -1e30f; s[mt][nt][3] = -1e30f; }
                }
            }
        }

        // ---- online softmax: max reduce (fp32), then P = exp2 in f16x2 ----
        float mn01[2][2], alpha01[2][2];
#pragma unroll
        for (int mt = 0; mt < 2; mt++) {
#pragma unroll
            for (int hh = 0; hh < 2; hh++) {
                float rm = -1e30f;
#pragma unroll
                for (int nt = 0; nt < 8; nt++) {
                    rm = fmaxf(rm, s[mt][nt][2 * hh]);
                    rm = fmaxf(rm, s[mt][nt][2 * hh + 1]);
                }
                rm = fmaxf(rm, __shfl_xor_sync(0xffffffffu, rm, 1));
                rm = fmaxf(rm, __shfl_xor_sync(0xffffffffu, rm, 2));
                float mold = mi[mt][hh];
                float mn = fmaxf(mold, rm);
                mn01[mt][hh] = mn;
                alpha01[mt][hh] = fast_exp2(mold - mn);
                mi[mt][hh] = mn;
                if (!__all_sync(0xffffffffu, mn == mold)) {
                    float a = alpha01[mt][hh];
#pragma unroll
                    for (int nt = 0; nt < 8; nt++) {
                        o[mt][nt][2 * hh]     *= a;
                        o[mt][nt][2 * hh + 1] *= a;
                    }
                }
            }
        }

        uint32_t ph[2][8][2];
#pragma unroll
        for (int mt = 0; mt < 2; mt++)
#pragma unroll
            for (int nt = 0; nt < 8; nt++) {
                ph[mt][nt][0] = ex2_h2(cvt2h(s[mt][nt][0] - mn01[mt][0], s[mt][nt][1] - mn01[mt][0]));
                ph[mt][nt][1] = ex2_h2(cvt2h(s[mt][nt][2] - mn01[mt][1], s[mt][nt][3] - mn01[mt][1]));
            }

        // ---- lsum (ones-MMA) + O += P V (V frags shared across mt) ----
        float ls[2][4] = {{0.f, 0.f, 0.f, 0.f}, {0.f, 0.f, 0.f, 0.f}};
#pragma unroll
        for (int kt = 0; kt < 4; kt++) {
            uint32_t ap0_[4] = {ph[0][2 * kt][0], ph[0][2 * kt][1],
                                ph[0][2 * kt + 1][0], ph[0][2 * kt + 1][1]};
            uint32_t ap1_[4] = {ph[1][2 * kt][0], ph[1][2 * kt][1],
                                ph[1][2 * kt + 1][0], ph[1][2 * kt + 1][1]};
            mma16816h(ls[0], ap0_, ones2);
            mma16816h(ls[1], ap1_, ones2);
#pragma unroll
            for (int np = 0; np < 4; np++) {
                uint32_t r4[4];
                ldsm4t(r4, kbc + 9216 + (uint32_t)(((kt * 16 + lr) * AP + np * 16 + lc) * 2));
                uint32_t vh0[2] = {r4[0], r4[1]}, vh1[2] = {r4[2], r4[3]};
                mma16816h(o[0][2 * np],     ap0_, vh0);
                mma16816h(o[0][2 * np + 1], ap0_, vh1);
                mma16816h(o[1][2 * np],     ap1_, vh0);
                mma16816h(o[1][2 * np + 1], ap1_, vh1);
            }
        }
#pragma unroll
        for (int mt = 0; mt < 2; mt++) {
            li[mt][0] = li[mt][0] * alpha01[mt][0] + ls[mt][0];
            li[mt][1] = li[mt][1] * alpha01[mt][1] + ls[mt][2];
        }
    }

    // ---- normalize + write single fp16 (feeds out-proj) ----
#pragma unroll
    for (int mt = 0; mt < 2; mt++) {
        float inv0 = __fdividef(1.0f, li[mt][0]);
        float inv1 = __fdividef(1.0f, li[mt][1]);
#pragma unroll
        for (int nt = 0; nt < 8; nt++) {
            int r = q0 + wid * 32 + mt * 16 + (lane >> 2);
            int c = h * DHD + nt * 8 + (lane & 3) * 2;
            *reinterpret_cast<uint32_t*>(og + (size_t)(bN + r) * DIMM + c) =
                h2pack(o[mt][nt][0] * inv0, o[mt][nt][1] * inv0);
            *reinterpret_cast<uint32_t*>(og + (size_t)(bN + r + 8) * DIMM + c) =
                h2pack(o[mt][nt][2] * inv1, o[mt][nt][3] * inv1);
        }
    }
}

// ---------------------------------------------------------------------------
extern "C" void kernel_launch(void* const* d_in, const int* in_sizes, int n_in,
                              void* d_out, int out_size)
{
    const float* x   = (const float*)d_in[0];
    const float* wq  = (const float*)d_in[1];
    const float* wkv = (const float*)d_in[2];
    const float* wo  = (const float*)d_in[3];
    const float* bo  = (const float*)d_in[4];
    const float* m_k = (const float*)d_in[5];
    const float* m_v = (const float*)d_in[6];
    float* out = (float*)d_out;

    __half *px, *pq, *pk, *pv, *po, *pw3, *pwo;
    cudaGetSymbolAddress((void**)&px,  g_x);
    cudaGetSymbolAddress((void**)&pq,  g_q);
    cudaGetSymbolAddress((void**)&pk,  g_k);
    cudaGetSymbolAddress((void**)&pv,  g_v);
    cudaGetSymbolAddress((void**)&po,  g_o);
    cudaGetSymbolAddress((void**)&pw3, g_w3);
    cudaGetSymbolAddress((void**)&pwo, g_wo);

    const int GEMM_SMEM = 2 * GST_B;                 // 73728
    const int ATTN_SMEM = 128 * AP * 2 + 2 * KVST_B; // 55296
    cudaFuncSetAttribute(mma_gemm_kernel, cudaFuncAttributeMaxDynamicSharedMemorySize, GEMM_SMEM);
    cudaFuncSetAttribute(mma_attn_kernel, cudaFuncAttributeMaxDynamicSharedMemorySize, ATTN_SMEM);

    // Prep
    convert_x_kernel<<<(MROWS * KDIM / 4 + 255) / 256, 256>>>(x, px, MROWS * KDIM);
    {
        dim3 grid(32, KDIM / 64);
        transpose_cvt_all<<<grid, 256>>>(wq, wkv, wo, pw3, pwo);
    }

    // Fused Q+K+V projection (N=1536), single-term fp16
    {
        dim3 grid(3 * DIMM / 128, MROWS / 128);
        mma_gemm_kernel<<<grid, 256, GEMM_SMEM>>>(px, pw3,
            nullptr, nullptr, pq, pk, pv, 0);
    }
    // Attention (4 warps, m32 x n64)
    {
        dim3 grid(NTOK / 128, NB * NH);
        mma_attn_kernel<<<grid, 128, ATTN_SMEM>>>(pq, pk, pv, m_k, m_v, po);
    }
    // Output projection (+bias) -> fp32
    {
        dim3 grid(DIMM / 128, MROWS / 128);
        mma_gemm_kernel<<<grid, 256, GEMM_SMEM>>>(po, pwo,
            out, bo, nullptr, nullptr, nullptr, 1);
    }
}